// round 1
// baseline (speedup 1.0000x reference)
#include <cuda_runtime.h>
#include <math.h>

#define Bb   2
#define Ll   2048
#define Dd   1024
#define Hh   16
#define HDh  64
#define NC   512
#define BLD  (Bb*Ll*Dd)     /* 4194304 */
#define NTOK (Bb*Hh*Ll)     /* 65536   */

// Intermediate buffers, layout [B, H, L, HD] (row-major, HD fastest)
__device__ float g_q   [NTOK*HDh];
__device__ float g_k   [NTOK*HDh];
__device__ float g_v   [NTOK*HDh];
__device__ float g_khat[NTOK*HDh];
__device__ float g_attn[NTOK*HDh];

// ---------------------------------------------------------------------------
// GEMM: C[r,e] = sum_k A[r,k] * W[e,k];  A = x [4096,1024], W [1024,1024]
// Stores into out[b,h,l,hd] with r=b*L+l, e=h*64+hd.
// 64x64 tile, BK=16, 256 threads, 4x4 micro-tile.
// ---------------------------------------------------------------------------
__global__ __launch_bounds__(256)
void gemm_qkv_kernel(const float* __restrict__ A, const float* __restrict__ W,
                     float* __restrict__ out) {
    __shared__ float As[16][68];
    __shared__ float Bs[16][68];
    int tid   = threadIdx.x;
    int r0    = blockIdx.y * 64;
    int n0    = blockIdx.x * 64;
    int mload = tid >> 2;
    int kq    = (tid & 3) * 4;
    int tx    = tid & 15, ty = tid >> 4;
    float acc[4][4] = {};

    for (int k0 = 0; k0 < Dd; k0 += 16) {
        float4 a = *(const float4*)(A + (size_t)(r0 + mload) * Dd + k0 + kq);
        float4 b = *(const float4*)(W + (size_t)(n0 + mload) * Dd + k0 + kq);
        As[kq+0][mload]=a.x; As[kq+1][mload]=a.y; As[kq+2][mload]=a.z; As[kq+3][mload]=a.w;
        Bs[kq+0][mload]=b.x; Bs[kq+1][mload]=b.y; Bs[kq+2][mload]=b.z; Bs[kq+3][mload]=b.w;
        __syncthreads();
        #pragma unroll
        for (int k = 0; k < 16; k++) {
            float4 av = *(const float4*)&As[k][ty*4];
            float4 bv = *(const float4*)&Bs[k][tx*4];
            float ar[4] = {av.x, av.y, av.z, av.w};
            float br[4] = {bv.x, bv.y, bv.z, bv.w};
            #pragma unroll
            for (int i = 0; i < 4; i++)
                #pragma unroll
                for (int j = 0; j < 4; j++)
                    acc[i][j] += ar[i] * br[j];
        }
        __syncthreads();
    }
    #pragma unroll
    for (int i = 0; i < 4; i++) {
        int r = r0 + ty*4 + i;
        int b = r >> 11, l = r & 2047;
        #pragma unroll
        for (int j = 0; j < 4; j++) {
            int e = n0 + tx*4 + j;
            int h = e >> 6, hd = e & 63;
            out[(((size_t)(b*Hh + h))*Ll + l)*HDh + hd] = acc[i][j];
        }
    }
}

// ---------------------------------------------------------------------------
// Output projection: out[b,l,e] = sum_c attn[b, c>>6, l, c&63] * Wo[e,c]
// ---------------------------------------------------------------------------
__global__ __launch_bounds__(256)
void gemm_out_kernel(const float* __restrict__ Wo, float* __restrict__ out) {
    __shared__ float As[16][68];
    __shared__ float Bs[16][68];
    int tid   = threadIdx.x;
    int r0    = blockIdx.y * 64;
    int n0    = blockIdx.x * 64;
    int mload = tid >> 2;
    int kq    = (tid & 3) * 4;
    int tx    = tid & 15, ty = tid >> 4;
    float acc[4][4] = {};

    for (int k0 = 0; k0 < Dd; k0 += 16) {
        int r  = r0 + mload;
        int b  = r >> 11, l = r & 2047;
        int c0 = k0 + kq;                 // head = c0>>6 constant over the float4
        float4 a = *(const float4*)(g_attn +
                     (((size_t)(b*Hh + (c0 >> 6)))*Ll + l)*HDh + (c0 & 63));
        float4 bv = *(const float4*)(Wo + (size_t)(n0 + mload) * Dd + c0);
        As[kq+0][mload]=a.x;  As[kq+1][mload]=a.y;  As[kq+2][mload]=a.z;  As[kq+3][mload]=a.w;
        Bs[kq+0][mload]=bv.x; Bs[kq+1][mload]=bv.y; Bs[kq+2][mload]=bv.z; Bs[kq+3][mload]=bv.w;
        __syncthreads();
        #pragma unroll
        for (int k = 0; k < 16; k++) {
            float4 av = *(const float4*)&As[k][ty*4];
            float4 bw = *(const float4*)&Bs[k][tx*4];
            float ar[4] = {av.x, av.y, av.z, av.w};
            float br[4] = {bw.x, bw.y, bw.z, bw.w};
            #pragma unroll
            for (int i = 0; i < 4; i++)
                #pragma unroll
                for (int j = 0; j < 4; j++)
                    acc[i][j] += ar[i] * br[j];
        }
        __syncthreads();
    }
    #pragma unroll
    for (int i = 0; i < 4; i++) {
        int r = r0 + ty*4 + i;
        #pragma unroll
        for (int j = 0; j < 4; j++) {
            int e = n0 + tx*4 + j;
            out[(size_t)r * Dd + e] = acc[i][j];
        }
    }
}

// ---------------------------------------------------------------------------
// VQ: per (b,h,l) argmin_c ||k - codebook[h,c]||^2 (dot form).
// Block = 128 rows of one (b,h); codes streamed through smem in chunks of 64.
// Writes k_hat, shortcodes (as float), and accumulates the commit loss.
// ---------------------------------------------------------------------------
__global__ __launch_bounds__(128)
void vq_kernel(const float* __restrict__ codebook, float* __restrict__ dout,
               int out_size) {
    __shared__ float Ks[128][65];
    __shared__ float Cs[64][68];
    __shared__ float c2s[64];
    __shared__ int   bestS[128];
    __shared__ float red[128];

    int tid = threadIdx.x;
    int bh  = blockIdx.y;
    int h   = bh & (Hh - 1);
    int l0  = blockIdx.x * 128;
    size_t kbase = ((size_t)bh * Ll + l0) * HDh;

    for (int idx = tid; idx < 128*64; idx += 128)
        Ks[idx >> 6][idx & 63] = g_k[kbase + idx];
    __syncthreads();

    float kr[64];
    float k0a = 0.f, k1a = 0.f, k2a = 0.f, k3a = 0.f;
    #pragma unroll
    for (int d = 0; d < 64; d += 4) {
        kr[d]   = Ks[tid][d];   k0a += kr[d]  *kr[d];
        kr[d+1] = Ks[tid][d+1]; k1a += kr[d+1]*kr[d+1];
        kr[d+2] = Ks[tid][d+2]; k2a += kr[d+2]*kr[d+2];
        kr[d+3] = Ks[tid][d+3]; k3a += kr[d+3]*kr[d+3];
    }
    float k2 = (k0a + k1a) + (k2a + k3a);

    float best = 3.4e38f;
    int bestc = 0;
    for (int cc = 0; cc < NC; cc += 64) {
        __syncthreads();
        for (int idx = tid; idx < 64*64; idx += 128)
            Cs[idx >> 6][idx & 63] =
                codebook[((size_t)h*NC + cc + (idx >> 6))*HDh + (idx & 63)];
        __syncthreads();
        if (tid < 64) {
            float s0=0,s1=0,s2=0,s3=0;
            #pragma unroll
            for (int d = 0; d < 64; d += 4) {
                float4 cv = *(const float4*)&Cs[tid][d];
                s0 += cv.x*cv.x; s1 += cv.y*cv.y; s2 += cv.z*cv.z; s3 += cv.w*cv.w;
            }
            c2s[tid] = (s0+s1)+(s2+s3);
        }
        __syncthreads();
        #pragma unroll 4
        for (int c = 0; c < 64; c++) {
            float p0=0,p1=0,p2=0,p3=0;
            #pragma unroll
            for (int d = 0; d < 64; d += 4) {
                float4 cv = *(const float4*)&Cs[c][d];
                p0 += kr[d]*cv.x; p1 += kr[d+1]*cv.y;
                p2 += kr[d+2]*cv.z; p3 += kr[d+3]*cv.w;
            }
            float dist = (k2 + c2s[c]) - 2.f*((p0+p1)+(p2+p3));
            if (dist < best) { best = dist; bestc = cc + c; }
        }
    }

    bestS[tid] = bestc;
    red[tid]   = best;
    __syncthreads();
    for (int s = 64; s > 0; s >>= 1) {
        if (tid < s) red[tid] += red[tid + s];
        __syncthreads();
    }
    if (tid == 0 && out_size >= BLD + 2) {
        float v = red[0] * (1.0f / (float)NTOK);
        atomicAdd(&dout[BLD],     v);   // l_commit
        atomicAdd(&dout[BLD + 1], v);   // l_codebook (identical forward value)
    }
    if (out_size >= BLD + 2 + NTOK)
        dout[BLD + 2 + (size_t)bh*Ll + l0 + tid] = (float)bestc;

    // k_hat = selected code rows (coalesced cooperative copy)
    for (int idx = tid; idx < 128*64; idx += 128) {
        int r = idx >> 6, d = idx & 63;
        g_khat[kbase + idx] = codebook[((size_t)h*NC + bestS[r])*HDh + d];
    }
}

// ---------------------------------------------------------------------------
// Causal attention, online softmax. 1 thread = 1 query row.
// Block: 128 query rows of one (b,h); keys streamed in 32-row smem tiles,
// only tiles with j0 <= max query row of the block (causality).
// ---------------------------------------------------------------------------
__global__ __launch_bounds__(128)
void attn_kernel() {
    __shared__ float Ks[32][68];
    __shared__ float Vs[32][68];

    int tid = threadIdx.x;
    int bh  = blockIdx.y;
    int i0  = blockIdx.x * 128;
    int i   = i0 + tid;
    size_t base = (size_t)bh * Ll * HDh;

    const float scale = 0.125f;  // 64^-0.5
    float qr[64];
    #pragma unroll
    for (int d = 0; d < 64; d += 4) {
        float4 t = *(const float4*)(g_q + base + (size_t)i*HDh + d);
        qr[d] = t.x*scale; qr[d+1] = t.y*scale; qr[d+2] = t.z*scale; qr[d+3] = t.w*scale;
    }

    float o_acc[64];
    #pragma unroll
    for (int d = 0; d < 64; d++) o_acc[d] = 0.f;
    float mrow = -1e30f, lrow = 0.f;

    int jend = i0 + 128;               // keys [0, i0+128) cover all rows' causal range
    for (int j0 = 0; j0 < jend; j0 += 32) {
        for (int idx = tid; idx < 32*64; idx += 128) {
            int r = idx >> 6, d = idx & 63;
            Ks[r][d] = g_khat[base + (size_t)(j0 + r)*HDh + d];
            Vs[r][d] = g_v   [base + (size_t)(j0 + r)*HDh + d];
        }
        __syncthreads();

        float s[32];
        float tmax = -1e30f;
        #pragma unroll
        for (int t = 0; t < 32; t++) {
            float p0=0,p1=0,p2=0,p3=0;
            #pragma unroll
            for (int d = 0; d < 64; d += 4) {
                float4 kk = *(const float4*)&Ks[t][d];
                p0 += qr[d]*kk.x; p1 += qr[d+1]*kk.y;
                p2 += qr[d+2]*kk.z; p3 += qr[d+3]*kk.w;
            }
            float sv = (p0+p1)+(p2+p3);
            if (j0 + t > i) sv = -1e30f;       // causal mask, matches reference
            s[t] = sv;
            tmax = fmaxf(tmax, sv);
        }

        float mnew = fmaxf(mrow, tmax);
        float corr = __expf(mrow - mnew);
        lrow *= corr;
        #pragma unroll
        for (int d = 0; d < 64; d++) o_acc[d] *= corr;

        #pragma unroll
        for (int t = 0; t < 32; t++) {
            float p = __expf(s[t] - mnew);
            lrow += p;
            #pragma unroll
            for (int d = 0; d < 64; d += 4) {
                float4 vv = *(const float4*)&Vs[t][d];
                o_acc[d]   += p*vv.x; o_acc[d+1] += p*vv.y;
                o_acc[d+2] += p*vv.z; o_acc[d+3] += p*vv.w;
            }
        }
        mrow = mnew;
        __syncthreads();
    }

    float inv = 1.0f / lrow;
    #pragma unroll
    for (int d = 0; d < 64; d += 4) {
        float4 t;
        t.x = o_acc[d]*inv; t.y = o_acc[d+1]*inv;
        t.z = o_acc[d+2]*inv; t.w = o_acc[d+3]*inv;
        *(float4*)(g_attn + base + (size_t)i*HDh + d) = t;
    }
}

__global__ void init_scalars(float* dout) {
    dout[BLD] = 0.f;
    dout[BLD + 1] = 0.f;
}

// ---------------------------------------------------------------------------
extern "C" void kernel_launch(void* const* d_in, const int* in_sizes, int n_in,
                              void* d_out, int out_size) {
    const float* x  = (const float*)d_in[0];
    const float* Wq = (const float*)d_in[1];
    const float* Wk = (const float*)d_in[2];
    const float* Wv = (const float*)d_in[3];
    const float* Wo = (const float*)d_in[4];
    const float* cb = (const float*)d_in[5];
    float* out = (float*)d_out;

    float *pq, *pk, *pv;
    cudaGetSymbolAddress((void**)&pq, g_q);
    cudaGetSymbolAddress((void**)&pk, g_k);
    cudaGetSymbolAddress((void**)&pv, g_v);

    dim3 gblk(256), ggrid(Dd/64, (Bb*Ll)/64);
    gemm_qkv_kernel<<<ggrid, gblk>>>(x, Wq, pq);
    gemm_qkv_kernel<<<ggrid, gblk>>>(x, Wk, pk);
    gemm_qkv_kernel<<<ggrid, gblk>>>(x, Wv, pv);

    if (out_size >= BLD + 2) init_scalars<<<1, 1>>>(out);
    vq_kernel<<<dim3(Ll/128, Bb*Hh), 128>>>(cb, out, out_size);
    attn_kernel<<<dim3(Ll/128, Bb*Hh), 128>>>();
    gemm_out_kernel<<<ggrid, gblk>>>(Wo, out);
}

// round 5
// speedup vs baseline: 1.2418x; 1.2418x over previous
#include <cuda_runtime.h>
#include <cuda_bf16.h>
#include <cstdint>
#include <math.h>

#define Bb   2
#define Ll   2048
#define Dd   1024
#define Hh   16
#define HDh  64
#define NC   512
#define BLD  (Bb*Ll*Dd)     /* 4194304 */
#define NTOK (Bb*Hh*Ll)     /* 65536   */

// Intermediate buffers, layout [B, H, L, HD]
__device__ float g_q   [NTOK*HDh];
__device__ float g_k   [NTOK*HDh];
__device__ float g_v   [NTOK*HDh];
__device__ float g_khat[NTOK*HDh];
__device__ float g_attn[NTOK*HDh];
__device__ float g_lred[512];

__device__ __forceinline__ uint32_t bfpack(float e0, float e1) {
    uint32_t r;
    asm("cvt.rn.bf16x2.f32 %0, %1, %2;" : "=r"(r) : "f"(e1), "f"(e0));
    return r;
}
__device__ __forceinline__ void mma_bf16(float* d, const uint32_t* a, const uint32_t* b) {
    asm volatile(
        "mma.sync.aligned.m16n8k16.row.col.f32.bf16.bf16.f32 "
        "{%0,%1,%2,%3},{%4,%5,%6,%7},{%8,%9},{%0,%1,%2,%3};"
        : "+f"(d[0]), "+f"(d[1]), "+f"(d[2]), "+f"(d[3])
        : "r"(a[0]), "r"(a[1]), "r"(a[2]), "r"(a[3]), "r"(b[0]), "r"(b[1]));
}

// ===========================================================================
// 3xBF16 split-precision GEMM (Q, V, Wo projections — smooth consumers):
//   D[r,e] = sum_k A[r,k]*W[e,k];  D = Ahi*Bhi + Ahi*Blo + Alo*Bhi
//   mode 0: A = x, scatter out to [B,H,L,HD]
//   mode 1: A gathered from g_attn, out row-major [r, e]
// ===========================================================================
#define PITCH 12
#define PLANE (128*PITCH)
#define STG   (4*PLANE)
#define PD    136

__global__ void __launch_bounds__(256)
gemm_mma_kernel(const float* __restrict__ A, const float* __restrict__ W,
                float* __restrict__ out, int mode) {
    __shared__ __align__(16) uint32_t smem[2*STG];   // 49152 B

    int tid  = threadIdx.x;
    int lane = tid & 31;
    int gid  = lane >> 2, tig = lane & 3;
    int warp = tid >> 5;
    int wm = (warp >> 1) * 32, wn = (warp & 1) * 64;
    int r0 = blockIdx.y * 128, n0 = blockIdx.x * 128;

    float4 va[2], vb[2];

    auto ldA = [&](int kb) {
        #pragma unroll
        for (int j = 0; j < 2; j++) {
            int idx = tid + j*256;
            int m = idx >> 2, kq = (idx & 3) * 4;
            if (mode == 0) {
                va[j] = *(const float4*)(A + (size_t)(r0 + m)*Dd + kb + kq);
            } else {
                int r = r0 + m, b = r >> 11, l = r & 2047;
                int c0 = kb + kq;
                va[j] = *(const float4*)(g_attn +
                          (((size_t)(b*Hh + (c0 >> 6)))*Ll + l)*HDh + (c0 & 63));
            }
        }
    };
    auto ldB = [&](int kb) {
        #pragma unroll
        for (int j = 0; j < 2; j++) {
            int idx = tid + j*256;
            int n = idx >> 2, kq = (idx & 3) * 4;
            vb[j] = *(const float4*)(W + (size_t)(n0 + n)*Dd + kb + kq);
        }
    };
    auto splitStore = [&](float4 v, uint32_t* hiP, uint32_t* loP, int m, int kq) {
        float hx = __bfloat162float(__float2bfloat16_rn(v.x));
        float hy = __bfloat162float(__float2bfloat16_rn(v.y));
        float hz = __bfloat162float(__float2bfloat16_rn(v.z));
        float hw = __bfloat162float(__float2bfloat16_rn(v.w));
        uint2 hiw = { bfpack(hx, hy), bfpack(hz, hw) };
        uint2 low = { bfpack(v.x - hx, v.y - hy), bfpack(v.z - hz, v.w - hw) };
        *(uint2*)&hiP[m*PITCH + (kq >> 1)] = hiw;
        *(uint2*)&loP[m*PITCH + (kq >> 1)] = low;
    };
    auto stAB = [&](int s) {
        uint32_t* base = smem + s*STG;
        #pragma unroll
        for (int j = 0; j < 2; j++) {
            int idx = tid + j*256;
            int m = idx >> 2, kq = (idx & 3) * 4;
            splitStore(va[j], base,           base + PLANE,   m, kq);
            splitStore(vb[j], base + 2*PLANE, base + 3*PLANE, m, kq);
        }
    };

    ldA(0); ldB(0);
    stAB(0);
    __syncthreads();

    float acc[2][8][4] = {};
    const int NIT = Dd / 16;   // 64
    for (int it = 0; it < NIT; it++) {
        int s = it & 1;
        if (it + 1 < NIT) { ldA((it+1)*16); ldB((it+1)*16); }
        const uint32_t* Ahi = smem + s*STG;
        const uint32_t* Alo = Ahi + PLANE;
        const uint32_t* Bhi = Ahi + 2*PLANE;
        const uint32_t* Blo = Ahi + 3*PLANE;

        uint32_t af[2][2][4];
        uint32_t bf[8][2][2];
        #pragma unroll
        for (int mt = 0; mt < 2; mt++) {
            int mr = wm + mt*16 + gid;
            af[mt][0][0] = Ahi[ mr     *PITCH + tig    ];
            af[mt][0][1] = Ahi[(mr + 8)*PITCH + tig    ];
            af[mt][0][2] = Ahi[ mr     *PITCH + tig + 4];
            af[mt][0][3] = Ahi[(mr + 8)*PITCH + tig + 4];
            af[mt][1][0] = Alo[ mr     *PITCH + tig    ];
            af[mt][1][1] = Alo[(mr + 8)*PITCH + tig    ];
            af[mt][1][2] = Alo[ mr     *PITCH + tig + 4];
            af[mt][1][3] = Alo[(mr + 8)*PITCH + tig + 4];
        }
        #pragma unroll
        for (int j = 0; j < 8; j++) {
            int nc = wn + j*8 + gid;
            bf[j][0][0] = Bhi[nc*PITCH + tig    ];
            bf[j][0][1] = Bhi[nc*PITCH + tig + 4];
            bf[j][1][0] = Blo[nc*PITCH + tig    ];
            bf[j][1][1] = Blo[nc*PITCH + tig + 4];
        }
        #pragma unroll
        for (int mt = 0; mt < 2; mt++)
            #pragma unroll
            for (int j = 0; j < 8; j++) {
                mma_bf16(acc[mt][j], af[mt][0], bf[j][0]);
                mma_bf16(acc[mt][j], af[mt][0], bf[j][1]);
                mma_bf16(acc[mt][j], af[mt][1], bf[j][0]);
            }

        if (it + 1 < NIT) stAB(s ^ 1);
        __syncthreads();
    }

    float* Ds = (float*)smem;
    #pragma unroll 1
    for (int half = 0; half < 2; half++) {
        __syncthreads();
        if ((wm >> 6) == half) {
            int lr0 = wm - half*64;
            #pragma unroll
            for (int mt = 0; mt < 2; mt++)
                #pragma unroll
                for (int j = 0; j < 8; j++) {
                    int lr  = lr0 + mt*16 + gid;
                    int col = wn + j*8 + tig*2;
                    *(float2*)&Ds[ lr     *PD + col] = make_float2(acc[mt][j][0], acc[mt][j][1]);
                    *(float2*)&Ds[(lr + 8)*PD + col] = make_float2(acc[mt][j][2], acc[mt][j][3]);
                }
        }
        __syncthreads();
        if (mode == 0) {
            int b = r0 >> 11, lb = r0 & 2047;
            #pragma unroll
            for (int i = 0; i < 8; i++) {
                int idx = tid + i*256;
                int lr = idx >> 5, c4 = (idx & 31) * 4;
                int e = n0 + c4, h = e >> 6, hd = e & 63;
                *(float4*)(out + (((size_t)(b*Hh + h))*Ll + lb + half*64 + lr)*HDh + hd)
                    = *(float4*)&Ds[lr*PD + c4];
            }
        } else {
            #pragma unroll
            for (int i = 0; i < 8; i++) {
                int idx = tid + i*256;
                int lr = idx >> 5, c4 = (idx & 31) * 4;
                *(float4*)(out + (size_t)(r0 + half*64 + lr)*Dd + n0 + c4)
                    = *(float4*)&Ds[lr*PD + c4];
            }
        }
    }
}

// ===========================================================================
// fp32 FFMA GEMM — K projection ONLY (feeds the tie-sensitive VQ argmin).
// Round-1 kernel: 64x64 tile, BK=16, 256 threads, 4x4 micro-tile.
// ===========================================================================
__global__ void __launch_bounds__(256)
gemm_f32_kernel(const float* __restrict__ A, const float* __restrict__ W,
                float* __restrict__ out) {
    __shared__ float As[16][68];
    __shared__ float Bs[16][68];
    int tid   = threadIdx.x;
    int r0    = blockIdx.y * 64;
    int n0    = blockIdx.x * 64;
    int mload = tid >> 2;
    int kq    = (tid & 3) * 4;
    int tx    = tid & 15, ty = tid >> 4;
    float acc[4][4] = {};

    for (int k0 = 0; k0 < Dd; k0 += 16) {
        float4 a = *(const float4*)(A + (size_t)(r0 + mload) * Dd + k0 + kq);
        float4 b = *(const float4*)(W + (size_t)(n0 + mload) * Dd + k0 + kq);
        As[kq+0][mload]=a.x; As[kq+1][mload]=a.y; As[kq+2][mload]=a.z; As[kq+3][mload]=a.w;
        Bs[kq+0][mload]=b.x; Bs[kq+1][mload]=b.y; Bs[kq+2][mload]=b.z; Bs[kq+3][mload]=b.w;
        __syncthreads();
        #pragma unroll
        for (int k = 0; k < 16; k++) {
            float4 av = *(const float4*)&As[k][ty*4];
            float4 bv = *(const float4*)&Bs[k][tx*4];
            float ar[4] = {av.x, av.y, av.z, av.w};
            float br[4] = {bv.x, bv.y, bv.z, bv.w};
            #pragma unroll
            for (int i = 0; i < 4; i++)
                #pragma unroll
                for (int j = 0; j < 4; j++)
                    acc[i][j] += ar[i] * br[j];
        }
        __syncthreads();
    }
    #pragma unroll
    for (int i = 0; i < 4; i++) {
        int r = r0 + ty*4 + i;
        int b = r >> 11, l = r & 2047;
        #pragma unroll
        for (int j = 0; j < 4; j++) {
            int e = n0 + tx*4 + j;
            int h = e >> 6, hd = e & 63;
            out[(((size_t)(b*Hh + h))*Ll + l)*HDh + hd] = acc[i][j];
        }
    }
}

// ===========================================================================
// VQ (fp32, unchanged)
// ===========================================================================
__global__ void __launch_bounds__(128)
vq_kernel(const float* __restrict__ codebook, float* __restrict__ dout,
          int out_size) {
    __shared__ float Ks[128][65];
    __shared__ float Cs[64][68];
    __shared__ float c2s[64];
    __shared__ int   bestS[128];
    __shared__ float red[128];

    int tid = threadIdx.x;
    int bh  = blockIdx.y;
    int h   = bh & (Hh - 1);
    int l0  = blockIdx.x * 128;
    size_t kbase = ((size_t)bh * Ll + l0) * HDh;

    for (int idx = tid; idx < 128*64; idx += 128)
        Ks[idx >> 6][idx & 63] = g_k[kbase + idx];
    __syncthreads();

    float kr[64];
    float k0a = 0.f, k1a = 0.f, k2a = 0.f, k3a = 0.f;
    #pragma unroll
    for (int d = 0; d < 64; d += 4) {
        kr[d]   = Ks[tid][d];   k0a += kr[d]  *kr[d];
        kr[d+1] = Ks[tid][d+1]; k1a += kr[d+1]*kr[d+1];
        kr[d+2] = Ks[tid][d+2]; k2a += kr[d+2]*kr[d+2];
        kr[d+3] = Ks[tid][d+3]; k3a += kr[d+3]*kr[d+3];
    }
    float k2 = (k0a + k1a) + (k2a + k3a);

    float best = 3.4e38f;
    int bestc = 0;
    for (int cc = 0; cc < NC; cc += 64) {
        __syncthreads();
        for (int idx = tid; idx < 64*64; idx += 128)
            Cs[idx >> 6][idx & 63] =
                codebook[((size_t)h*NC + cc + (idx >> 6))*HDh + (idx & 63)];
        __syncthreads();
        if (tid < 64) {
            float s0=0,s1=0,s2=0,s3=0;
            #pragma unroll
            for (int d = 0; d < 64; d += 4) {
                float4 cv = *(const float4*)&Cs[tid][d];
                s0 += cv.x*cv.x; s1 += cv.y*cv.y; s2 += cv.z*cv.z; s3 += cv.w*cv.w;
            }
            c2s[tid] = (s0+s1)+(s2+s3);
        }
        __syncthreads();
        #pragma unroll 4
        for (int c = 0; c < 64; c++) {
            float p0=0,p1=0,p2=0,p3=0;
            #pragma unroll
            for (int d = 0; d < 64; d += 4) {
                float4 cv = *(const float4*)&Cs[c][d];
                p0 += kr[d]*cv.x; p1 += kr[d+1]*cv.y;
                p2 += kr[d+2]*cv.z; p3 += kr[d+3]*cv.w;
            }
            float dist = (k2 + c2s[c]) - 2.f*((p0+p1)+(p2+p3));
            if (dist < best) { best = dist; bestc = cc + c; }
        }
    }

    bestS[tid] = bestc;
    red[tid]   = best;
    __syncthreads();
    for (int s = 64; s > 0; s >>= 1) {
        if (tid < s) red[tid] += red[tid + s];
        __syncthreads();
    }
    if (tid == 0)
        g_lred[blockIdx.y * 16 + blockIdx.x] = red[0];
    if (out_size >= BLD + 2 + NTOK)
        dout[BLD + 2 + (size_t)bh*Ll + l0 + tid] = (float)bestc;

    for (int idx = tid; idx < 128*64; idx += 128) {
        int r = idx >> 6, d = idx & 63;
        g_khat[kbase + idx] = codebook[((size_t)h*NC + bestS[r])*HDh + d];
    }
}

__global__ void __launch_bounds__(512)
finalize_loss(float* dout, int out_size) {
    __shared__ float red[512];
    int tid = threadIdx.x;
    red[tid] = g_lred[tid];
    __syncthreads();
    for (int s = 256; s > 0; s >>= 1) {
        if (tid < s) red[tid] += red[tid + s];
        __syncthreads();
    }
    if (tid == 0 && out_size >= BLD + 2) {
        float v = red[0] * (1.0f / (float)NTOK);
        dout[BLD]     = v;
        dout[BLD + 1] = v;
    }
}

// ===========================================================================
// Causal attention, online softmax (fp32, unchanged this round)
// ===========================================================================
__global__ void __launch_bounds__(128)
attn_kernel() {
    __shared__ float Ks[32][68];
    __shared__ float Vs[32][68];

    int tid = threadIdx.x;
    int bh  = blockIdx.y;
    int i0  = blockIdx.x * 128;
    int i   = i0 + tid;
    size_t base = (size_t)bh * Ll * HDh;

    const float scale = 0.125f;
    float qr[64];
    #pragma unroll
    for (int d = 0; d < 64; d += 4) {
        float4 t = *(const float4*)(g_q + base + (size_t)i*HDh + d);
        qr[d] = t.x*scale; qr[d+1] = t.y*scale; qr[d+2] = t.z*scale; qr[d+3] = t.w*scale;
    }

    float o_acc[64];
    #pragma unroll
    for (int d = 0; d < 64; d++) o_acc[d] = 0.f;
    float mrow = -1e30f, lrow = 0.f;

    int jend = i0 + 128;
    for (int j0 = 0; j0 < jend; j0 += 32) {
        for (int idx = tid; idx < 32*64; idx += 128) {
            int r = idx >> 6, d = idx & 63;
            Ks[r][d] = g_khat[base + (size_t)(j0 + r)*HDh + d];
            Vs[r][d] = g_v   [base + (size_t)(j0 + r)*HDh + d];
        }
        __syncthreads();

        float s[32];
        float tmax = -1e30f;
        #pragma unroll
        for (int t = 0; t < 32; t++) {
            float p0=0,p1=0,p2=0,p3=0;
            #pragma unroll
            for (int d = 0; d < 64; d += 4) {
                float4 kk = *(const float4*)&Ks[t][d];
                p0 += qr[d]*kk.x; p1 += qr[d+1]*kk.y;
                p2 += qr[d+2]*kk.z; p3 += qr[d+3]*kk.w;
            }
            float sv = (p0+p1)+(p2+p3);
            if (j0 + t > i) sv = -1e30f;
            s[t] = sv;
            tmax = fmaxf(tmax, sv);
        }

        float mnew = fmaxf(mrow, tmax);
        float corr = __expf(mrow - mnew);
        lrow *= corr;
        #pragma unroll
        for (int d = 0; d < 64; d++) o_acc[d] *= corr;

        #pragma unroll
        for (int t = 0; t < 32; t++) {
            float p = __expf(s[t] - mnew);
            lrow += p;
            #pragma unroll
            for (int d = 0; d < 64; d += 4) {
                float4 vv = *(const float4*)&Vs[t][d];
                o_acc[d]   += p*vv.x; o_acc[d+1] += p*vv.y;
                o_acc[d+2] += p*vv.z; o_acc[d+3] += p*vv.w;
            }
        }
        mrow = mnew;
        __syncthreads();
    }

    float inv = 1.0f / lrow;
    #pragma unroll
    for (int d = 0; d < 64; d += 4) {
        float4 t;
        t.x = o_acc[d]*inv; t.y = o_acc[d+1]*inv;
        t.z = o_acc[d+2]*inv; t.w = o_acc[d+3]*inv;
        *(float4*)(g_attn + base + (size_t)i*HDh + d) = t;
    }
}

// ===========================================================================
extern "C" void kernel_launch(void* const* d_in, const int* in_sizes, int n_in,
                              void* d_out, int out_size) {
    const float* x  = (const float*)d_in[0];
    const float* Wq = (const float*)d_in[1];
    const float* Wk = (const float*)d_in[2];
    const float* Wv = (const float*)d_in[3];
    const float* Wo = (const float*)d_in[4];
    const float* cb = (const float*)d_in[5];
    float* out = (float*)d_out;

    float *pq, *pk, *pv;
    cudaGetSymbolAddress((void**)&pq, g_q);
    cudaGetSymbolAddress((void**)&pk, g_k);
    cudaGetSymbolAddress((void**)&pv, g_v);

    dim3 ggrid(Dd / 128, (Bb * Ll) / 128);       // (8, 32)  bf16x3 tiles
    dim3 fgrid(Dd / 64, (Bb * Ll) / 64);         // (16, 64) fp32 tiles

    gemm_mma_kernel<<<ggrid, 256>>>(x, Wq, pq, 0);   // Q  (smooth)
    gemm_mma_kernel<<<ggrid, 256>>>(x, Wv, pv, 0);   // V  (smooth)
    gemm_f32_kernel<<<fgrid, 256>>>(x, Wk, pk);      // K  (argmin-sensitive: fp32)

    vq_kernel<<<dim3(Ll/128, Bb*Hh), 128>>>(cb, out, out_size);
    finalize_loss<<<1, 512>>>(out, out_size);
    attn_kernel<<<dim3(Ll/128, Bb*Hh), 128>>>();     // launch #6 -> ncu -s5 target
    gemm_mma_kernel<<<ggrid, 256>>>(Wo, Wo, out, 1); // Wo (smooth)
}

// round 6
// speedup vs baseline: 2.1194x; 1.7067x over previous
#include <cuda_runtime.h>
#include <cuda_bf16.h>
#include <cstdint>
#include <math.h>

#define Bb   2
#define Ll   2048
#define Dd   1024
#define Hh   16
#define HDh  64
#define NC   512
#define BLD  (Bb*Ll*Dd)     /* 4194304 */
#define NTOK (Bb*Hh*Ll)     /* 65536   */

// Intermediate buffers, layout [B, H, L, HD]
__device__ float g_q   [NTOK*HDh];
__device__ float g_k   [NTOK*HDh];
__device__ float g_v   [NTOK*HDh];
__device__ float g_khat[NTOK*HDh];
__device__ float g_attn[NTOK*HDh];
__device__ float g_lred[512];

__device__ __forceinline__ uint32_t bfpack(float e0, float e1) {
    uint32_t r;
    asm("cvt.rn.bf16x2.f32 %0, %1, %2;" : "=r"(r) : "f"(e1), "f"(e0));
    return r;
}
__device__ __forceinline__ float tob(float x) {
    return __bfloat162float(__float2bfloat16_rn(x));
}
__device__ __forceinline__ void mma_bf16(float* d, const uint32_t* a, const uint32_t* b) {
    asm volatile(
        "mma.sync.aligned.m16n8k16.row.col.f32.bf16.bf16.f32 "
        "{%0,%1,%2,%3},{%4,%5,%6,%7},{%8,%9},{%0,%1,%2,%3};"
        : "+f"(d[0]), "+f"(d[1]), "+f"(d[2]), "+f"(d[3])
        : "r"(a[0]), "r"(a[1]), "r"(a[2]), "r"(a[3]), "r"(b[0]), "r"(b[1]));
}

// ===========================================================================
// 3xBF16 split-precision GEMM (Q, V, Wo projections — smooth consumers)
// ===========================================================================
#define PITCH 12
#define PLANE (128*PITCH)
#define STG   (4*PLANE)
#define PD    136

__global__ void __launch_bounds__(256)
gemm_mma_kernel(const float* __restrict__ A, const float* __restrict__ W,
                float* __restrict__ out, int mode) {
    __shared__ __align__(16) uint32_t smem[2*STG];   // 49152 B

    int tid  = threadIdx.x;
    int lane = tid & 31;
    int gid  = lane >> 2, tig = lane & 3;
    int warp = tid >> 5;
    int wm = (warp >> 1) * 32, wn = (warp & 1) * 64;
    int r0 = blockIdx.y * 128, n0 = blockIdx.x * 128;

    float4 va[2], vb[2];

    auto ldA = [&](int kb) {
        #pragma unroll
        for (int j = 0; j < 2; j++) {
            int idx = tid + j*256;
            int m = idx >> 2, kq = (idx & 3) * 4;
            if (mode == 0) {
                va[j] = *(const float4*)(A + (size_t)(r0 + m)*Dd + kb + kq);
            } else {
                int r = r0 + m, b = r >> 11, l = r & 2047;
                int c0 = kb + kq;
                va[j] = *(const float4*)(g_attn +
                          (((size_t)(b*Hh + (c0 >> 6)))*Ll + l)*HDh + (c0 & 63));
            }
        }
    };
    auto ldB = [&](int kb) {
        #pragma unroll
        for (int j = 0; j < 2; j++) {
            int idx = tid + j*256;
            int n = idx >> 2, kq = (idx & 3) * 4;
            vb[j] = *(const float4*)(W + (size_t)(n0 + n)*Dd + kb + kq);
        }
    };
    auto splitStore = [&](float4 v, uint32_t* hiP, uint32_t* loP, int m, int kq) {
        float hx = tob(v.x), hy = tob(v.y), hz = tob(v.z), hw = tob(v.w);
        uint2 hiw = { bfpack(hx, hy), bfpack(hz, hw) };
        uint2 low = { bfpack(v.x - hx, v.y - hy), bfpack(v.z - hz, v.w - hw) };
        *(uint2*)&hiP[m*PITCH + (kq >> 1)] = hiw;
        *(uint2*)&loP[m*PITCH + (kq >> 1)] = low;
    };
    auto stAB = [&](int s) {
        uint32_t* base = smem + s*STG;
        #pragma unroll
        for (int j = 0; j < 2; j++) {
            int idx = tid + j*256;
            int m = idx >> 2, kq = (idx & 3) * 4;
            splitStore(va[j], base,           base + PLANE,   m, kq);
            splitStore(vb[j], base + 2*PLANE, base + 3*PLANE, m, kq);
        }
    };

    ldA(0); ldB(0);
    stAB(0);
    __syncthreads();

    float acc[2][8][4] = {};
    const int NIT = Dd / 16;
    for (int it = 0; it < NIT; it++) {
        int s = it & 1;
        if (it + 1 < NIT) { ldA((it+1)*16); ldB((it+1)*16); }
        const uint32_t* Ahi = smem + s*STG;
        const uint32_t* Alo = Ahi + PLANE;
        const uint32_t* Bhi = Ahi + 2*PLANE;
        const uint32_t* Blo = Ahi + 3*PLANE;

        uint32_t af[2][2][4];
        uint32_t bf[8][2][2];
        #pragma unroll
        for (int mt = 0; mt < 2; mt++) {
            int mr = wm + mt*16 + gid;
            af[mt][0][0] = Ahi[ mr     *PITCH + tig    ];
            af[mt][0][1] = Ahi[(mr + 8)*PITCH + tig    ];
            af[mt][0][2] = Ahi[ mr     *PITCH + tig + 4];
            af[mt][0][3] = Ahi[(mr + 8)*PITCH + tig + 4];
            af[mt][1][0] = Alo[ mr     *PITCH + tig    ];
            af[mt][1][1] = Alo[(mr + 8)*PITCH + tig    ];
            af[mt][1][2] = Alo[ mr     *PITCH + tig + 4];
            af[mt][1][3] = Alo[(mr + 8)*PITCH + tig + 4];
        }
        #pragma unroll
        for (int j = 0; j < 8; j++) {
            int nc = wn + j*8 + gid;
            bf[j][0][0] = Bhi[nc*PITCH + tig    ];
            bf[j][0][1] = Bhi[nc*PITCH + tig + 4];
            bf[j][1][0] = Blo[nc*PITCH + tig    ];
            bf[j][1][1] = Blo[nc*PITCH + tig + 4];
        }
        #pragma unroll
        for (int mt = 0; mt < 2; mt++)
            #pragma unroll
            for (int j = 0; j < 8; j++) {
                mma_bf16(acc[mt][j], af[mt][0], bf[j][0]);
                mma_bf16(acc[mt][j], af[mt][0], bf[j][1]);
                mma_bf16(acc[mt][j], af[mt][1], bf[j][0]);
            }

        if (it + 1 < NIT) stAB(s ^ 1);
        __syncthreads();
    }

    float* Ds = (float*)smem;
    #pragma unroll 1
    for (int half = 0; half < 2; half++) {
        __syncthreads();
        if ((wm >> 6) == half) {
            int lr0 = wm - half*64;
            #pragma unroll
            for (int mt = 0; mt < 2; mt++)
                #pragma unroll
                for (int j = 0; j < 8; j++) {
                    int lr  = lr0 + mt*16 + gid;
                    int col = wn + j*8 + tig*2;
                    *(float2*)&Ds[ lr     *PD + col] = make_float2(acc[mt][j][0], acc[mt][j][1]);
                    *(float2*)&Ds[(lr + 8)*PD + col] = make_float2(acc[mt][j][2], acc[mt][j][3]);
                }
        }
        __syncthreads();
        if (mode == 0) {
            int b = r0 >> 11, lb = r0 & 2047;
            #pragma unroll
            for (int i = 0; i < 8; i++) {
                int idx = tid + i*256;
                int lr = idx >> 5, c4 = (idx & 31) * 4;
                int e = n0 + c4, h = e >> 6, hd = e & 63;
                *(float4*)(out + (((size_t)(b*Hh + h))*Ll + lb + half*64 + lr)*HDh + hd)
                    = *(float4*)&Ds[lr*PD + c4];
            }
        } else {
            #pragma unroll
            for (int i = 0; i < 8; i++) {
                int idx = tid + i*256;
                int lr = idx >> 5, c4 = (idx & 31) * 4;
                *(float4*)(out + (size_t)(r0 + half*64 + lr)*Dd + n0 + c4)
                    = *(float4*)&Ds[lr*PD + c4];
            }
        }
    }
}

// ===========================================================================
// fp32 FFMA GEMM — K projection ONLY (argmin-sensitive)
// ===========================================================================
__global__ void __launch_bounds__(256)
gemm_f32_kernel(const float* __restrict__ A, const float* __restrict__ W,
                float* __restrict__ out) {
    __shared__ float As[16][68];
    __shared__ float Bs[16][68];
    int tid   = threadIdx.x;
    int r0    = blockIdx.y * 64;
    int n0    = blockIdx.x * 64;
    int mload = tid >> 2;
    int kq    = (tid & 3) * 4;
    int tx    = tid & 15, ty = tid >> 4;
    float acc[4][4] = {};

    for (int k0 = 0; k0 < Dd; k0 += 16) {
        float4 a = *(const float4*)(A + (size_t)(r0 + mload) * Dd + k0 + kq);
        float4 b = *(const float4*)(W + (size_t)(n0 + mload) * Dd + k0 + kq);
        As[kq+0][mload]=a.x; As[kq+1][mload]=a.y; As[kq+2][mload]=a.z; As[kq+3][mload]=a.w;
        Bs[kq+0][mload]=b.x; Bs[kq+1][mload]=b.y; Bs[kq+2][mload]=b.z; Bs[kq+3][mload]=b.w;
        __syncthreads();
        #pragma unroll
        for (int k = 0; k < 16; k++) {
            float4 av = *(const float4*)&As[k][ty*4];
            float4 bv = *(const float4*)&Bs[k][tx*4];
            float ar[4] = {av.x, av.y, av.z, av.w};
            float br[4] = {bv.x, bv.y, bv.z, bv.w};
            #pragma unroll
            for (int i = 0; i < 4; i++)
                #pragma unroll
                for (int j = 0; j < 4; j++)
                    acc[i][j] += ar[i] * br[j];
        }
        __syncthreads();
    }
    #pragma unroll
    for (int i = 0; i < 4; i++) {
        int r = r0 + ty*4 + i;
        int b = r >> 11, l = r & 2047;
        #pragma unroll
        for (int j = 0; j < 4; j++) {
            int e = n0 + tx*4 + j;
            int h = e >> 6, hd = e & 63;
            out[(((size_t)(b*Hh + h))*Ll + l)*HDh + hd] = acc[i][j];
        }
    }
}

// ===========================================================================
// VQ (fp32, unchanged)
// ===========================================================================
__global__ void __launch_bounds__(128)
vq_kernel(const float* __restrict__ codebook, float* __restrict__ dout,
          int out_size) {
    __shared__ float Ks[128][65];
    __shared__ float Cs[64][68];
    __shared__ float c2s[64];
    __shared__ int   bestS[128];
    __shared__ float red[128];

    int tid = threadIdx.x;
    int bh  = blockIdx.y;
    int h   = bh & (Hh - 1);
    int l0  = blockIdx.x * 128;
    size_t kbase = ((size_t)bh * Ll + l0) * HDh;

    for (int idx = tid; idx < 128*64; idx += 128)
        Ks[idx >> 6][idx & 63] = g_k[kbase + idx];
    __syncthreads();

    float kr[64];
    float k0a = 0.f, k1a = 0.f, k2a = 0.f, k3a = 0.f;
    #pragma unroll
    for (int d = 0; d < 64; d += 4) {
        kr[d]   = Ks[tid][d];   k0a += kr[d]  *kr[d];
        kr[d+1] = Ks[tid][d+1]; k1a += kr[d+1]*kr[d+1];
        kr[d+2] = Ks[tid][d+2]; k2a += kr[d+2]*kr[d+2];
        kr[d+3] = Ks[tid][d+3]; k3a += kr[d+3]*kr[d+3];
    }
    float k2 = (k0a + k1a) + (k2a + k3a);

    float best = 3.4e38f;
    int bestc = 0;
    for (int cc = 0; cc < NC; cc += 64) {
        __syncthreads();
        for (int idx = tid; idx < 64*64; idx += 128)
            Cs[idx >> 6][idx & 63] =
                codebook[((size_t)h*NC + cc + (idx >> 6))*HDh + (idx & 63)];
        __syncthreads();
        if (tid < 64) {
            float s0=0,s1=0,s2=0,s3=0;
            #pragma unroll
            for (int d = 0; d < 64; d += 4) {
                float4 cv = *(const float4*)&Cs[tid][d];
                s0 += cv.x*cv.x; s1 += cv.y*cv.y; s2 += cv.z*cv.z; s3 += cv.w*cv.w;
            }
            c2s[tid] = (s0+s1)+(s2+s3);
        }
        __syncthreads();
        #pragma unroll 4
        for (int c = 0; c < 64; c++) {
            float p0=0,p1=0,p2=0,p3=0;
            #pragma unroll
            for (int d = 0; d < 64; d += 4) {
                float4 cv = *(const float4*)&Cs[c][d];
                p0 += kr[d]*cv.x; p1 += kr[d+1]*cv.y;
                p2 += kr[d+2]*cv.z; p3 += kr[d+3]*cv.w;
            }
            float dist = (k2 + c2s[c]) - 2.f*((p0+p1)+(p2+p3));
            if (dist < best) { best = dist; bestc = cc + c; }
        }
    }

    bestS[tid] = bestc;
    red[tid]   = best;
    __syncthreads();
    for (int s = 64; s > 0; s >>= 1) {
        if (tid < s) red[tid] += red[tid + s];
        __syncthreads();
    }
    if (tid == 0)
        g_lred[blockIdx.y * 16 + blockIdx.x] = red[0];
    if (out_size >= BLD + 2 + NTOK)
        dout[BLD + 2 + (size_t)bh*Ll + l0 + tid] = (float)bestc;

    for (int idx = tid; idx < 128*64; idx += 128) {
        int r = idx >> 6, d = idx & 63;
        g_khat[kbase + idx] = codebook[((size_t)h*NC + bestS[r])*HDh + d];
    }
}

__global__ void __launch_bounds__(512)
finalize_loss(float* dout, int out_size) {
    __shared__ float red[512];
    int tid = threadIdx.x;
    red[tid] = g_lred[tid];
    __syncthreads();
    for (int s = 256; s > 0; s >>= 1) {
        if (tid < s) red[tid] += red[tid + s];
        __syncthreads();
    }
    if (tid == 0 && out_size >= BLD + 2) {
        float v = red[0] * (1.0f / (float)NTOK);
        dout[BLD]     = v;
        dout[BLD + 1] = v;
    }
}

// ===========================================================================
// bf16x3 mma flash attention.
// Block = 128 query rows of one (b,h), 8 warps, 16 rows per warp.
// Key tiles of 64. K smem [key][hd-pair], V smem transposed [hd][key-pair],
// both as interleaved (hi,lo) bf16x2 uint2 words, pitch 36 uint2.
// S-accum fragments reused directly as P A-fragments (FA2 register trick).
// ===========================================================================
#define KVP 36   /* uint2 pitch */

__global__ void __launch_bounds__(256)
attn_mma_kernel() {
    __shared__ uint2 Ksm[64*KVP];
    __shared__ uint2 Vsm[64*KVP];

    int tid  = threadIdx.x;
    int lane = tid & 31;
    int gid  = lane >> 2, tig = lane & 3;
    int warp = tid >> 5;
    int bh   = blockIdx.y;
    int i0   = blockIdx.x * 128;
    int row_start = i0 + warp * 16;
    int r0g  = row_start + gid;
    size_t base = (size_t)bh * Ll * HDh;

    // ---- Q fragments (scaled), hi/lo split, register-resident ----
    const float scale = 0.125f;
    uint32_t qh[4][4], ql[4][4];
    #pragma unroll
    for (int kb = 0; kb < 4; kb++) {
        #pragma unroll
        for (int cc = 0; cc < 2; cc++)
            #pragma unroll
            for (int rr = 0; rr < 2; rr++) {
                int row = r0g + rr*8;
                int col = kb*16 + tig*2 + cc*8;
                float2 v = *(const float2*)(g_q + base + (size_t)row*HDh + col);
                v.x *= scale; v.y *= scale;
                float hx = tob(v.x), hy = tob(v.y);
                int r = cc*2 + rr;
                qh[kb][r] = bfpack(hx, hy);
                ql[kb][r] = bfpack(v.x - hx, v.y - hy);
            }
    }

    float of[8][4] = {};
    float m0 = -1e30f, m1 = -1e30f, l0 = 0.f, l1 = 0.f;

    for (int j0 = 0; j0 < i0 + 128; j0 += 64) {
        // ---- load K tile: [key][hd-pair] ----
        #pragma unroll
        for (int p = 0; p < 4; p++) {
            int idx = tid + p*256;
            int key = idx >> 4, c4 = (idx & 15) * 4;
            float4 kv = *(const float4*)(g_khat + base + (size_t)(j0 + key)*HDh + c4);
            float hx = tob(kv.x), hy = tob(kv.y), hz = tob(kv.z), hw = tob(kv.w);
            Ksm[key*KVP + (c4>>1)    ] = make_uint2(bfpack(hx, hy), bfpack(kv.x-hx, kv.y-hy));
            Ksm[key*KVP + (c4>>1) + 1] = make_uint2(bfpack(hz, hw), bfpack(kv.z-hz, kv.w-hw));
        }
        // ---- load V tile transposed: [hd][key-pair] ----
        #pragma unroll
        for (int p = 0; p < 2; p++) {
            int idx = tid + p*256;
            int kp = idx & 31, c4 = (idx >> 5) * 4;
            float4 a = *(const float4*)(g_v + base + (size_t)(j0 + 2*kp    )*HDh + c4);
            float4 b = *(const float4*)(g_v + base + (size_t)(j0 + 2*kp + 1)*HDh + c4);
            float ae[4] = {a.x, a.y, a.z, a.w};
            float be[4] = {b.x, b.y, b.z, b.w};
            #pragma unroll
            for (int e = 0; e < 4; e++) {
                float ha = tob(ae[e]), hb = tob(be[e]);
                Vsm[(c4+e)*KVP + kp] = make_uint2(bfpack(ha, hb), bfpack(ae[e]-ha, be[e]-hb));
            }
        }
        __syncthreads();

        if (j0 <= row_start + 15) {       // warp-uniform: any unmasked work?
            // ---- S = Q K^T ----
            float sc[8][4] = {};
            #pragma unroll
            for (int kb = 0; kb < 4; kb++)
                #pragma unroll
                for (int nj = 0; nj < 8; nj++) {
                    uint2 b0 = Ksm[(nj*8+gid)*KVP + kb*8 + tig];
                    uint2 b1 = Ksm[(nj*8+gid)*KVP + kb*8 + tig + 4];
                    uint32_t bhr[2] = {b0.x, b1.x}, blr[2] = {b0.y, b1.y};
                    mma_bf16(sc[nj], qh[kb], bhr);
                    mma_bf16(sc[nj], qh[kb], blr);
                    mma_bf16(sc[nj], ql[kb], bhr);
                }

            // ---- causal mask (diagonal tiles only) ----
            if (j0 + 63 > row_start) {
                #pragma unroll
                for (int nj = 0; nj < 8; nj++)
                    #pragma unroll
                    for (int e = 0; e < 2; e++) {
                        int col = j0 + nj*8 + tig*2 + e;
                        if (col > r0g)     sc[nj][e]     = -1e30f;
                        if (col > r0g + 8) sc[nj][2 + e] = -1e30f;
                    }
            }

            // ---- online softmax update ----
            float tm0 = -1e30f, tm1 = -1e30f;
            #pragma unroll
            for (int nj = 0; nj < 8; nj++) {
                tm0 = fmaxf(tm0, fmaxf(sc[nj][0], sc[nj][1]));
                tm1 = fmaxf(tm1, fmaxf(sc[nj][2], sc[nj][3]));
            }
            tm0 = fmaxf(tm0, __shfl_xor_sync(0xffffffff, tm0, 1));
            tm0 = fmaxf(tm0, __shfl_xor_sync(0xffffffff, tm0, 2));
            tm1 = fmaxf(tm1, __shfl_xor_sync(0xffffffff, tm1, 1));
            tm1 = fmaxf(tm1, __shfl_xor_sync(0xffffffff, tm1, 2));

            float mn0 = fmaxf(m0, tm0), mn1 = fmaxf(m1, tm1);
            float cr0 = __expf(m0 - mn0), cr1 = __expf(m1 - mn1);
            float rs0 = 0.f, rs1 = 0.f;
            #pragma unroll
            for (int nj = 0; nj < 8; nj++) {
                sc[nj][0] = __expf(sc[nj][0] - mn0);
                sc[nj][1] = __expf(sc[nj][1] - mn0);
                sc[nj][2] = __expf(sc[nj][2] - mn1);
                sc[nj][3] = __expf(sc[nj][3] - mn1);
                rs0 += sc[nj][0] + sc[nj][1];
                rs1 += sc[nj][2] + sc[nj][3];
            }
            rs0 += __shfl_xor_sync(0xffffffff, rs0, 1);
            rs0 += __shfl_xor_sync(0xffffffff, rs0, 2);
            rs1 += __shfl_xor_sync(0xffffffff, rs1, 1);
            rs1 += __shfl_xor_sync(0xffffffff, rs1, 2);
            l0 = l0*cr0 + rs0;
            l1 = l1*cr1 + rs1;
            m0 = mn0; m1 = mn1;
            #pragma unroll
            for (int nj = 0; nj < 8; nj++) {
                of[nj][0] *= cr0; of[nj][1] *= cr0;
                of[nj][2] *= cr1; of[nj][3] *= cr1;
            }

            // ---- O += P V (P frags straight from S accum frags) ----
            #pragma unroll
            for (int kb = 0; kb < 4; kb++) {
                float p00 = sc[2*kb][0],   p01 = sc[2*kb][1];
                float p10 = sc[2*kb][2],   p11 = sc[2*kb][3];
                float p20 = sc[2*kb+1][0], p21 = sc[2*kb+1][1];
                float p30 = sc[2*kb+1][2], p31 = sc[2*kb+1][3];
                float h00 = tob(p00), h01 = tob(p01), h10 = tob(p10), h11 = tob(p11);
                float h20 = tob(p20), h21 = tob(p21), h30 = tob(p30), h31 = tob(p31);
                uint32_t ph[4] = { bfpack(h00,h01), bfpack(h10,h11),
                                   bfpack(h20,h21), bfpack(h30,h31) };
                uint32_t pl[4] = { bfpack(p00-h00, p01-h01), bfpack(p10-h10, p11-h11),
                                   bfpack(p20-h20, p21-h21), bfpack(p30-h30, p31-h31) };
                #pragma unroll
                for (int nj = 0; nj < 8; nj++) {
                    uint2 b0 = Vsm[(nj*8+gid)*KVP + kb*8 + tig];
                    uint2 b1 = Vsm[(nj*8+gid)*KVP + kb*8 + tig + 4];
                    uint32_t vh[2] = {b0.x, b1.x}, vl[2] = {b0.y, b1.y};
                    mma_bf16(of[nj], ph, vh);
                    mma_bf16(of[nj], ph, vl);
                    mma_bf16(of[nj], pl, vh);
                }
            }
        }
        __syncthreads();
    }

    // ---- normalize + store ----
    float inv0 = 1.0f / l0, inv1 = 1.0f / l1;
    #pragma unroll
    for (int nj = 0; nj < 8; nj++) {
        *(float2*)(g_attn + base + (size_t)r0g*HDh + nj*8 + tig*2)
            = make_float2(of[nj][0]*inv0, of[nj][1]*inv0);
        *(float2*)(g_attn + base + (size_t)(r0g+8)*HDh + nj*8 + tig*2)
            = make_float2(of[nj][2]*inv1, of[nj][3]*inv1);
    }
}

// ===========================================================================
extern "C" void kernel_launch(void* const* d_in, const int* in_sizes, int n_in,
                              void* d_out, int out_size) {
    const float* x  = (const float*)d_in[0];
    const float* Wq = (const float*)d_in[1];
    const float* Wk = (const float*)d_in[2];
    const float* Wv = (const float*)d_in[3];
    const float* Wo = (const float*)d_in[4];
    const float* cb = (const float*)d_in[5];
    float* out = (float*)d_out;

    float *pq, *pk, *pv;
    cudaGetSymbolAddress((void**)&pq, g_q);
    cudaGetSymbolAddress((void**)&pk, g_k);
    cudaGetSymbolAddress((void**)&pv, g_v);

    dim3 ggrid(Dd / 128, (Bb * Ll) / 128);       // bf16x3 tiles
    dim3 fgrid(Dd / 64, (Bb * Ll) / 64);         // fp32 tiles

    gemm_mma_kernel<<<ggrid, 256>>>(x, Wq, pq, 0);   // Q  (smooth)
    gemm_mma_kernel<<<ggrid, 256>>>(x, Wv, pv, 0);   // V  (smooth)
    gemm_f32_kernel<<<fgrid, 256>>>(x, Wk, pk);      // K  (argmin-sensitive)

    vq_kernel<<<dim3(Ll/128, Bb*Hh), 128>>>(cb, out, out_size);
    finalize_loss<<<1, 512>>>(out, out_size);
    attn_mma_kernel<<<dim3(Ll/128, Bb*Hh), 256>>>(); // launch #6 -> ncu target
    gemm_mma_kernel<<<ggrid, 256>>>(Wo, Wo, out, 1); // Wo (smooth)
}

// round 8
// speedup vs baseline: 2.1849x; 1.0309x over previous
#include <cuda_runtime.h>
#include <cuda_bf16.h>
#include <cstdint>
#include <math.h>

#define Bb   2
#define Ll   2048
#define Dd   1024
#define Hh   16
#define HDh  64
#define NC   512
#define BLD  (Bb*Ll*Dd)     /* 4194304 */
#define NTOK (Bb*Hh*Ll)     /* 65536   */

// Intermediates
__device__ float g_q   [NTOK*HDh];                 // [B,H,L,HD] fp32
__device__ float g_k   [NTOK*HDh];                 // [B,H,L,HD] fp32 (VQ input)
__device__ float g_attn[NTOK*HDh];                 // [B,H,L,HD] fp32
__device__ float g_lred[512];
__device__ uint2 g_cbs    [Hh*NC*32];              // split codebook [h][c][hd/2]
__device__ uint2 g_khat_hl[(size_t)Bb*Hh*Ll*32];   // [bh][l][hd/2] (hi,lo) bf16x2
__device__ uint2 g_vt     [(size_t)Bb*Hh*HDh*(Ll/2)]; // [bh][hd][l/2] (hi,lo)

__device__ __forceinline__ uint32_t bfpack(float e0, float e1) {
    uint32_t r;
    asm("cvt.rn.bf16x2.f32 %0, %1, %2;" : "=r"(r) : "f"(e1), "f"(e0));
    return r;
}
__device__ __forceinline__ float tob(float x) {
    return __bfloat162float(__float2bfloat16_rn(x));
}
__device__ __forceinline__ void mma_bf16(float* d, const uint32_t* a, const uint32_t* b) {
    asm volatile(
        "mma.sync.aligned.m16n8k16.row.col.f32.bf16.bf16.f32 "
        "{%0,%1,%2,%3},{%4,%5,%6,%7},{%8,%9},{%0,%1,%2,%3};"
        : "+f"(d[0]), "+f"(d[1]), "+f"(d[2]), "+f"(d[3])
        : "r"(a[0]), "r"(a[1]), "r"(a[2]), "r"(a[3]), "r"(b[0]), "r"(b[1]));
}

// ===========================================================================
// 3xBF16 split GEMM. D[r,e] = sum_k A[r,k]*W[e,k]
//   mode 0: A=x, scatter fp32 out to [B,H,L,HD]           (Q)
//   mode 1: A gathered from g_attn, out row-major [r,e]   (final out)
//   mode 2: A=x, write split-bf16 TRANSPOSED V to g_vt    (V)
// ===========================================================================
#define PITCH 12
#define PLANE (128*PITCH)
#define STG   (4*PLANE)
#define PD    136

__global__ void __launch_bounds__(256)
gemm_mma_kernel(const float* __restrict__ A, const float* __restrict__ W,
                float* __restrict__ out, int mode) {
    __shared__ __align__(16) uint32_t smem[2*STG];   // 49152 B

    int tid  = threadIdx.x;
    int lane = tid & 31;
    int gid  = lane >> 2, tig = lane & 3;
    int warp = tid >> 5;
    int wm = (warp >> 1) * 32, wn = (warp & 1) * 64;
    int r0 = blockIdx.y * 128, n0 = blockIdx.x * 128;

    float4 va[2], vb[2];

    auto ldA = [&](int kb) {
        #pragma unroll
        for (int j = 0; j < 2; j++) {
            int idx = tid + j*256;
            int m = idx >> 2, kq = (idx & 3) * 4;
            if (mode != 1) {
                va[j] = *(const float4*)(A + (size_t)(r0 + m)*Dd + kb + kq);
            } else {
                int r = r0 + m, b = r >> 11, l = r & 2047;
                int c0 = kb + kq;
                va[j] = *(const float4*)(g_attn +
                          (((size_t)(b*Hh + (c0 >> 6)))*Ll + l)*HDh + (c0 & 63));
            }
        }
    };
    auto ldB = [&](int kb) {
        #pragma unroll
        for (int j = 0; j < 2; j++) {
            int idx = tid + j*256;
            int n = idx >> 2, kq = (idx & 3) * 4;
            vb[j] = *(const float4*)(W + (size_t)(n0 + n)*Dd + kb + kq);
        }
    };
    auto splitStore = [&](float4 v, uint32_t* hiP, uint32_t* loP, int m, int kq) {
        float hx = tob(v.x), hy = tob(v.y), hz = tob(v.z), hw = tob(v.w);
        uint2 hiw = { bfpack(hx, hy), bfpack(hz, hw) };
        uint2 low = { bfpack(v.x - hx, v.y - hy), bfpack(v.z - hz, v.w - hw) };
        *(uint2*)&hiP[m*PITCH + (kq >> 1)] = hiw;
        *(uint2*)&loP[m*PITCH + (kq >> 1)] = low;
    };
    auto stAB = [&](int s) {
        uint32_t* base = smem + s*STG;
        #pragma unroll
        for (int j = 0; j < 2; j++) {
            int idx = tid + j*256;
            int m = idx >> 2, kq = (idx & 3) * 4;
            splitStore(va[j], base,           base + PLANE,   m, kq);
            splitStore(vb[j], base + 2*PLANE, base + 3*PLANE, m, kq);
        }
    };

    ldA(0); ldB(0);
    stAB(0);
    __syncthreads();

    float acc[2][8][4] = {};
    const int NIT = Dd / 16;
    for (int it = 0; it < NIT; it++) {
        int s = it & 1;
        if (it + 1 < NIT) { ldA((it+1)*16); ldB((it+1)*16); }
        const uint32_t* Ahi = smem + s*STG;
        const uint32_t* Alo = Ahi + PLANE;
        const uint32_t* Bhi = Ahi + 2*PLANE;
        const uint32_t* Blo = Ahi + 3*PLANE;

        uint32_t af[2][2][4];
        uint32_t bf[8][2][2];
        #pragma unroll
        for (int mt = 0; mt < 2; mt++) {
            int mr = wm + mt*16 + gid;
            af[mt][0][0] = Ahi[ mr     *PITCH + tig    ];
            af[mt][0][1] = Ahi[(mr + 8)*PITCH + tig    ];
            af[mt][0][2] = Ahi[ mr     *PITCH + tig + 4];
            af[mt][0][3] = Ahi[(mr + 8)*PITCH + tig + 4];
            af[mt][1][0] = Alo[ mr     *PITCH + tig    ];
            af[mt][1][1] = Alo[(mr + 8)*PITCH + tig    ];
            af[mt][1][2] = Alo[ mr     *PITCH + tig + 4];
            af[mt][1][3] = Alo[(mr + 8)*PITCH + tig + 4];
        }
        #pragma unroll
        for (int j = 0; j < 8; j++) {
            int nc = wn + j*8 + gid;
            bf[j][0][0] = Bhi[nc*PITCH + tig    ];
            bf[j][0][1] = Bhi[nc*PITCH + tig + 4];
            bf[j][1][0] = Blo[nc*PITCH + tig    ];
            bf[j][1][1] = Blo[nc*PITCH + tig + 4];
        }
        #pragma unroll
        for (int mt = 0; mt < 2; mt++)
            #pragma unroll
            for (int j = 0; j < 8; j++) {
                mma_bf16(acc[mt][j], af[mt][0], bf[j][0]);
                mma_bf16(acc[mt][j], af[mt][0], bf[j][1]);
                mma_bf16(acc[mt][j], af[mt][1], bf[j][0]);
            }

        if (it + 1 < NIT) stAB(s ^ 1);
        __syncthreads();
    }

    float* Ds = (float*)smem;
    #pragma unroll 1
    for (int half = 0; half < 2; half++) {
        __syncthreads();
        if (mode == 2) {
            // transposed staging: Dt[col][lr], pitch 66 (even, conflict-light)
            if ((wm >> 6) == half) {
                int lr0 = wm - half*64;
                #pragma unroll
                for (int mt = 0; mt < 2; mt++)
                    #pragma unroll
                    for (int j = 0; j < 8; j++) {
                        int lr  = lr0 + mt*16 + gid;
                        int col = wn + j*8 + tig*2;
                        Ds[ col   *66 + lr    ] = acc[mt][j][0];
                        Ds[(col+1)*66 + lr    ] = acc[mt][j][1];
                        Ds[ col   *66 + lr + 8] = acc[mt][j][2];
                        Ds[(col+1)*66 + lr + 8] = acc[mt][j][3];
                    }
            }
            __syncthreads();
            int b = r0 >> 11, lb = r0 & 2047;
            int lpbase = (lb + half*64) >> 1;
            #pragma unroll
            for (int i = 0; i < 16; i++) {
                int idx = tid + i*256;
                int lp = idx & 31, c = idx >> 5;          // c: 0..127
                float2 v = *(const float2*)&Ds[c*66 + 2*lp];
                float hx = tob(v.x), hy = tob(v.y);
                uint2 o = { bfpack(hx, hy), bfpack(v.x - hx, v.y - hy) };
                int bh = b*Hh + (n0 >> 6) + (c >> 6);
                g_vt[((size_t)bh*HDh + (c & 63))*(Ll/2) + lpbase + lp] = o;
            }
            continue;
        }
        if ((wm >> 6) == half) {
            int lr0 = wm - half*64;
            #pragma unroll
            for (int mt = 0; mt < 2; mt++)
                #pragma unroll
                for (int j = 0; j < 8; j++) {
                    int lr  = lr0 + mt*16 + gid;
                    int col = wn + j*8 + tig*2;
                    *(float2*)&Ds[ lr     *PD + col] = make_float2(acc[mt][j][0], acc[mt][j][1]);
                    *(float2*)&Ds[(lr + 8)*PD + col] = make_float2(acc[mt][j][2], acc[mt][j][3]);
                }
        }
        __syncthreads();
        if (mode == 0) {
            int b = r0 >> 11, lb = r0 & 2047;
            #pragma unroll
            for (int i = 0; i < 8; i++) {
                int idx = tid + i*256;
                int lr = idx >> 5, c4 = (idx & 31) * 4;
                int e = n0 + c4, h = e >> 6, hd = e & 63;
                *(float4*)(out + (((size_t)(b*Hh + h))*Ll + lb + half*64 + lr)*HDh + hd)
                    = *(float4*)&Ds[lr*PD + c4];
            }
        } else {
            #pragma unroll
            for (int i = 0; i < 8; i++) {
                int idx = tid + i*256;
                int lr = idx >> 5, c4 = (idx & 31) * 4;
                *(float4*)(out + (size_t)(r0 + half*64 + lr)*Dd + n0 + c4)
                    = *(float4*)&Ds[lr*PD + c4];
            }
        }
    }
}

// ===========================================================================
// fp32 FFMA GEMM — K projection (PROVEN argmin-exact; do not change numerics)
// ===========================================================================
__global__ void __launch_bounds__(256)
gemm_f32_kernel(const float* __restrict__ A, const float* __restrict__ W,
                float* __restrict__ out) {
    __shared__ float As[16][68];
    __shared__ float Bs[16][68];
    int tid   = threadIdx.x;
    int r0    = blockIdx.y * 64;
    int n0    = blockIdx.x * 64;
    int mload = tid >> 2;
    int kq    = (tid & 3) * 4;
    int tx    = tid & 15, ty = tid >> 4;
    float acc[4][4] = {};

    for (int k0 = 0; k0 < Dd; k0 += 16) {
        float4 a = *(const float4*)(A + (size_t)(r0 + mload) * Dd + k0 + kq);
        float4 b = *(const float4*)(W + (size_t)(n0 + mload) * Dd + k0 + kq);
        As[kq+0][mload]=a.x; As[kq+1][mload]=a.y; As[kq+2][mload]=a.z; As[kq+3][mload]=a.w;
        Bs[kq+0][mload]=b.x; Bs[kq+1][mload]=b.y; Bs[kq+2][mload]=b.z; Bs[kq+3][mload]=b.w;
        __syncthreads();
        #pragma unroll
        for (int k = 0; k < 16; k++) {
            float4 av = *(const float4*)&As[k][ty*4];
            float4 bv = *(const float4*)&Bs[k][tx*4];
            float ar[4] = {av.x, av.y, av.z, av.w};
            float br[4] = {bv.x, bv.y, bv.z, bv.w};
            #pragma unroll
            for (int i = 0; i < 4; i++)
                #pragma unroll
                for (int j = 0; j < 4; j++)
                    acc[i][j] += ar[i] * br[j];
        }
        __syncthreads();
    }
    #pragma unroll
    for (int i = 0; i < 4; i++) {
        int r = r0 + ty*4 + i;
        int b = r >> 11, l = r & 2047;
        #pragma unroll
        for (int j = 0; j < 4; j++) {
            int e = n0 + tx*4 + j;
            int h = e >> 6, hd = e & 63;
            out[(((size_t)(b*Hh + h))*Ll + l)*HDh + hd] = acc[i][j];
        }
    }
}

// ===========================================================================
// codebook -> split-bf16 uint2 (one-time prep)
// ===========================================================================
__global__ void __launch_bounds__(256)
cb_split_kernel(const float* __restrict__ codebook) {
    int t = blockIdx.x * 256 + threadIdx.x;      // < Hh*NC*32
    int row = t >> 5, pr = t & 31;
    float2 v = *(const float2*)(codebook + (size_t)row*HDh + 2*pr);
    float hx = tob(v.x), hy = tob(v.y);
    g_cbs[t] = make_uint2(bfpack(hx, hy), bfpack(v.x - hx, v.y - hy));
}

// ===========================================================================
// VQ (fp32 math UNCHANGED); khat emitted as split-bf16 via codebook gather
// ===========================================================================
__global__ void __launch_bounds__(128)
vq_kernel(const float* __restrict__ codebook, float* __restrict__ dout,
          int out_size) {
    __shared__ float Ks[128][65];
    __shared__ float Cs[64][68];
    __shared__ float c2s[64];
    __shared__ int   bestS[128];
    __shared__ float red[128];

    int tid = threadIdx.x;
    int bh  = blockIdx.y;
    int h   = bh & (Hh - 1);
    int l0  = blockIdx.x * 128;
    size_t kbase = ((size_t)bh * Ll + l0) * HDh;

    for (int idx = tid; idx < 128*64; idx += 128)
        Ks[idx >> 6][idx & 63] = g_k[kbase + idx];
    __syncthreads();

    float kr[64];
    float k0a = 0.f, k1a = 0.f, k2a = 0.f, k3a = 0.f;
    #pragma unroll
    for (int d = 0; d < 64; d += 4) {
        kr[d]   = Ks[tid][d];   k0a += kr[d]  *kr[d];
        kr[d+1] = Ks[tid][d+1]; k1a += kr[d+1]*kr[d+1];
        kr[d+2] = Ks[tid][d+2]; k2a += kr[d+2]*kr[d+2];
        kr[d+3] = Ks[tid][d+3]; k3a += kr[d+3]*kr[d+3];
    }
    float k2 = (k0a + k1a) + (k2a + k3a);

    float best = 3.4e38f;
    int bestc = 0;
    for (int cc = 0; cc < NC; cc += 64) {
        __syncthreads();
        for (int idx = tid; idx < 64*64; idx += 128)
            Cs[idx >> 6][idx & 63] =
                codebook[((size_t)h*NC + cc + (idx >> 6))*HDh + (idx & 63)];
        __syncthreads();
        if (tid < 64) {
            float s0=0,s1=0,s2=0,s3=0;
            #pragma unroll
            for (int d = 0; d < 64; d += 4) {
                float4 cv = *(const float4*)&Cs[tid][d];
                s0 += cv.x*cv.x; s1 += cv.y*cv.y; s2 += cv.z*cv.z; s3 += cv.w*cv.w;
            }
            c2s[tid] = (s0+s1)+(s2+s3);
        }
        __syncthreads();
        #pragma unroll 4
        for (int c = 0; c < 64; c++) {
            float p0=0,p1=0,p2=0,p3=0;
            #pragma unroll
            for (int d = 0; d < 64; d += 4) {
                float4 cv = *(const float4*)&Cs[c][d];
                p0 += kr[d]*cv.x; p1 += kr[d+1]*cv.y;
                p2 += kr[d+2]*cv.z; p3 += kr[d+3]*cv.w;
            }
            float dist = (k2 + c2s[c]) - 2.f*((p0+p1)+(p2+p3));
            if (dist < best) { best = dist; bestc = cc + c; }
        }
    }

    bestS[tid] = bestc;
    red[tid]   = best;
    __syncthreads();
    for (int s = 64; s > 0; s >>= 1) {
        if (tid < s) red[tid] += red[tid + s];
        __syncthreads();
    }
    if (tid == 0)
        g_lred[blockIdx.y * 16 + blockIdx.x] = red[0];
    if (out_size >= BLD + 2 + NTOK)
        dout[BLD + 2 + (size_t)bh*Ll + l0 + tid] = (float)bestc;

    // k_hat in split-bf16 form: gather pre-split codebook rows
    for (int idx = tid; idx < 128*32; idx += 128) {
        int r = idx >> 5, pr = idx & 31;
        g_khat_hl[((size_t)bh*Ll + l0 + r)*32 + pr]
            = g_cbs[((size_t)h*NC + bestS[r])*32 + pr];
    }
}

__global__ void __launch_bounds__(512)
finalize_loss(float* dout, int out_size) {
    __shared__ float red[512];
    int tid = threadIdx.x;
    red[tid] = g_lred[tid];
    __syncthreads();
    for (int s = 256; s > 0; s >>= 1) {
        if (tid < s) red[tid] += red[tid + s];
        __syncthreads();
    }
    if (tid == 0 && out_size >= BLD + 2) {
        float v = red[0] * (1.0f / (float)NTOK);
        dout[BLD]     = v;
        dout[BLD + 1] = v;
    }
}

// ===========================================================================
// bf16x3 mma flash attention — smem fills are now pure coalesced copies.
// Heavy query tiles launched first (reversed i0).
// ===========================================================================
#define KVP 36   /* uint2 pitch */

__global__ void __launch_bounds__(256)
attn_mma_kernel() {
    __shared__ uint2 Ksm[64*KVP];
    __shared__ uint2 Vsm[64*KVP];

    int tid  = threadIdx.x;
    int lane = tid & 31;
    int gid  = lane >> 2, tig = lane & 3;
    int warp = tid >> 5;
    int bh   = blockIdx.y;
    int i0   = ((int)gridDim.x - 1 - (int)blockIdx.x) * 128;   // heavy first
    int row_start = i0 + warp * 16;
    int r0g  = row_start + gid;
    size_t base = (size_t)bh * Ll * HDh;

    const float scale = 0.125f;
    uint32_t qh[4][4], ql[4][4];
    #pragma unroll
    for (int kb = 0; kb < 4; kb++) {
        #pragma unroll
        for (int cc = 0; cc < 2; cc++)
            #pragma unroll
            for (int rr = 0; rr < 2; rr++) {
                int row = r0g + rr*8;
                int col = kb*16 + tig*2 + cc*8;
                float2 v = *(const float2*)(g_q + base + (size_t)row*HDh + col);
                v.x *= scale; v.y *= scale;
                float hx = tob(v.x), hy = tob(v.y);
                int r = cc*2 + rr;
                qh[kb][r] = bfpack(hx, hy);
                ql[kb][r] = bfpack(v.x - hx, v.y - hy);
            }
    }

    float of[8][4] = {};
    float m0 = -1e30f, m1 = -1e30f, l0 = 0.f, l1 = 0.f;

    const uint2* kh = g_khat_hl + (size_t)bh * Ll * 32;
    const uint2* vt = g_vt     + (size_t)bh * HDh * (Ll/2);

    for (int j0 = 0; j0 < i0 + 128; j0 += 64) {
        // K tile copy: [key][hd-pair]
        #pragma unroll
        for (int p = 0; p < 8; p++) {
            int idx = tid + p*256;
            int key = idx >> 5, pr = idx & 31;
            Ksm[key*KVP + pr] = kh[(size_t)(j0 + key)*32 + pr];
        }
        // V tile copy (already transposed + key-paired): [hd][key-pair]
        #pragma unroll
        for (int p = 0; p < 8; p++) {
            int idx = tid + p*256;
            int hd = idx >> 5, kp = idx & 31;
            Vsm[hd*KVP + kp] = vt[(size_t)hd*(Ll/2) + (j0 >> 1) + kp];
        }
        __syncthreads();

        if (j0 <= row_start + 15) {
            float sc[8][4] = {};
            #pragma unroll
            for (int kb = 0; kb < 4; kb++)
                #pragma unroll
                for (int nj = 0; nj < 8; nj++) {
                    uint2 b0 = Ksm[(nj*8+gid)*KVP + kb*8 + tig];
                    uint2 b1 = Ksm[(nj*8+gid)*KVP + kb*8 + tig + 4];
                    uint32_t bhr[2] = {b0.x, b1.x}, blr[2] = {b0.y, b1.y};
                    mma_bf16(sc[nj], qh[kb], bhr);
                    mma_bf16(sc[nj], qh[kb], blr);
                    mma_bf16(sc[nj], ql[kb], bhr);
                }

            if (j0 + 63 > row_start) {
                #pragma unroll
                for (int nj = 0; nj < 8; nj++)
                    #pragma unroll
                    for (int e = 0; e < 2; e++) {
                        int col = j0 + nj*8 + tig*2 + e;
                        if (col > r0g)     sc[nj][e]     = -1e30f;
                        if (col > r0g + 8) sc[nj][2 + e] = -1e30f;
                    }
            }

            float tm0 = -1e30f, tm1 = -1e30f;
            #pragma unroll
            for (int nj = 0; nj < 8; nj++) {
                tm0 = fmaxf(tm0, fmaxf(sc[nj][0], sc[nj][1]));
                tm1 = fmaxf(tm1, fmaxf(sc[nj][2], sc[nj][3]));
            }
            tm0 = fmaxf(tm0, __shfl_xor_sync(0xffffffff, tm0, 1));
            tm0 = fmaxf(tm0, __shfl_xor_sync(0xffffffff, tm0, 2));
            tm1 = fmaxf(tm1, __shfl_xor_sync(0xffffffff, tm1, 1));
            tm1 = fmaxf(tm1, __shfl_xor_sync(0xffffffff, tm1, 2));

            float mn0 = fmaxf(m0, tm0), mn1 = fmaxf(m1, tm1);
            float cr0 = __expf(m0 - mn0), cr1 = __expf(m1 - mn1);
            float rs0 = 0.f, rs1 = 0.f;
            #pragma unroll
            for (int nj = 0; nj < 8; nj++) {
                sc[nj][0] = __expf(sc[nj][0] - mn0);
                sc[nj][1] = __expf(sc[nj][1] - mn0);
                sc[nj][2] = __expf(sc[nj][2] - mn1);
                sc[nj][3] = __expf(sc[nj][3] - mn1);
                rs0 += sc[nj][0] + sc[nj][1];
                rs1 += sc[nj][2] + sc[nj][3];
            }
            rs0 += __shfl_xor_sync(0xffffffff, rs0, 1);
            rs0 += __shfl_xor_sync(0xffffffff, rs0, 2);
            rs1 += __shfl_xor_sync(0xffffffff, rs1, 1);
            rs1 += __shfl_xor_sync(0xffffffff, rs1, 2);
            l0 = l0*cr0 + rs0;
            l1 = l1*cr1 + rs1;
            m0 = mn0; m1 = mn1;
            #pragma unroll
            for (int nj = 0; nj < 8; nj++) {
                of[nj][0] *= cr0; of[nj][1] *= cr0;
                of[nj][2] *= cr1; of[nj][3] *= cr1;
            }

            #pragma unroll
            for (int kb = 0; kb < 4; kb++) {
                float p00 = sc[2*kb][0],   p01 = sc[2*kb][1];
                float p10 = sc[2*kb][2],   p11 = sc[2*kb][3];
                float p20 = sc[2*kb+1][0], p21 = sc[2*kb+1][1];
                float p30 = sc[2*kb+1][2], p31 = sc[2*kb+1][3];
                float h00 = tob(p00), h01 = tob(p01), h10 = tob(p10), h11 = tob(p11);
                float h20 = tob(p20), h21 = tob(p21), h30 = tob(p30), h31 = tob(p31);
                uint32_t ph[4] = { bfpack(h00,h01), bfpack(h10,h11),
                                   bfpack(h20,h21), bfpack(h30,h31) };
                uint32_t pl[4] = { bfpack(p00-h00, p01-h01), bfpack(p10-h10, p11-h11),
                                   bfpack(p20-h20, p21-h21), bfpack(p30-h30, p31-h31) };
                #pragma unroll
                for (int nj = 0; nj < 8; nj++) {
                    uint2 b0 = Vsm[(nj*8+gid)*KVP + kb*8 + tig];
                    uint2 b1 = Vsm[(nj*8+gid)*KVP + kb*8 + tig + 4];
                    uint32_t vh[2] = {b0.x, b1.x}, vl[2] = {b0.y, b1.y};
                    mma_bf16(of[nj], ph, vh);
                    mma_bf16(of[nj], ph, vl);
                    mma_bf16(of[nj], pl, vh);
                }
            }
        }
        __syncthreads();
    }

    float inv0 = 1.0f / l0, inv1 = 1.0f / l1;
    #pragma unroll
    for (int nj = 0; nj < 8; nj++) {
        *(float2*)(g_attn + base + (size_t)r0g*HDh + nj*8 + tig*2)
            = make_float2(of[nj][0]*inv0, of[nj][1]*inv0);
        *(float2*)(g_attn + base + (size_t)(r0g+8)*HDh + nj*8 + tig*2)
            = make_float2(of[nj][2]*inv1, of[nj][3]*inv1);
    }
}

// ===========================================================================
extern "C" void kernel_launch(void* const* d_in, const int* in_sizes, int n_in,
                              void* d_out, int out_size) {
    const float* x  = (const float*)d_in[0];
    const float* Wq = (const float*)d_in[1];
    const float* Wk = (const float*)d_in[2];
    const float* Wv = (const float*)d_in[3];
    const float* Wo = (const float*)d_in[4];
    const float* cb = (const float*)d_in[5];
    float* out = (float*)d_out;

    float *pq, *pk;
    cudaGetSymbolAddress((void**)&pq, g_q);
    cudaGetSymbolAddress((void**)&pk, g_k);

    dim3 ggrid(Dd / 128, (Bb * Ll) / 128);   // (8, 32)
    dim3 fgrid(Dd / 64, (Bb * Ll) / 64);     // (16, 64)

    cb_split_kernel<<<(Hh*NC*32)/256, 256>>>(cb);
    gemm_mma_kernel<<<ggrid, 256>>>(x, Wq, pq, 0);        // Q  (bf16x3)
    gemm_mma_kernel<<<ggrid, 256>>>(x, Wv, nullptr, 2);   // V  (bf16x3 -> g_vt)
    gemm_f32_kernel<<<fgrid, 256>>>(x, Wk, pk);           // K  (fp32, argmin-exact)

    vq_kernel<<<dim3(Ll/128, Bb*Hh), 128>>>(cb, out, out_size);
    finalize_loss<<<1, 512>>>(out, out_size);
    attn_mma_kernel<<<dim3(Ll/128, Bb*Hh), 256>>>();
    gemm_mma_kernel<<<ggrid, 256>>>(Wo, Wo, out, 1);      // Wo (bf16x3)
}

// round 9
// speedup vs baseline: 2.2529x; 1.0311x over previous
#include <cuda_runtime.h>
#include <cuda_bf16.h>
#include <cstdint>
#include <math.h>

#define Bb   2
#define Ll   2048
#define Dd   1024
#define Hh   16
#define HDh  64
#define NC   512
#define BLD  (Bb*Ll*Dd)     /* 4194304 */
#define NTOK (Bb*Hh*Ll)     /* 65536   */

// Intermediates
__device__ float g_q   [NTOK*HDh];                 // [B,H,L,HD] fp32
__device__ float g_k   [NTOK*HDh];                 // [B,H,L,HD] fp32 (VQ input)
__device__ float g_attn[NTOK*HDh];                 // [B,H,L,HD] fp32
__device__ float g_lred[512];
__device__ uint2 g_cbs    [Hh*NC*32];              // split codebook [h][c][hd/2]
__device__ uint2 g_khat_hl[(size_t)Bb*Hh*Ll*32];   // [bh][l][hd/2] (hi,lo) bf16x2
__device__ uint2 g_vt     [(size_t)Bb*Hh*HDh*(Ll/2)]; // [bh][hd][l/2] (hi,lo)

__device__ __forceinline__ uint32_t bfpack(float e0, float e1) {
    uint32_t r;
    asm("cvt.rn.bf16x2.f32 %0, %1, %2;" : "=r"(r) : "f"(e1), "f"(e0));
    return r;
}
__device__ __forceinline__ float tob(float x) {
    return __bfloat162float(__float2bfloat16_rn(x));
}
__device__ __forceinline__ void mma_bf16(float* d, const uint32_t* a, const uint32_t* b) {
    asm volatile(
        "mma.sync.aligned.m16n8k16.row.col.f32.bf16.bf16.f32 "
        "{%0,%1,%2,%3},{%4,%5,%6,%7},{%8,%9},{%0,%1,%2,%3};"
        : "+f"(d[0]), "+f"(d[1]), "+f"(d[2]), "+f"(d[3])
        : "r"(a[0]), "r"(a[1]), "r"(a[2]), "r"(a[3]), "r"(b[0]), "r"(b[1]));
}

// ===========================================================================
// 3xBF16 split GEMM. D[r,e] = sum_k A[r,k]*W[e,k]
//   mode 0: A=x, scatter fp32 out to [B,H,L,HD]           (Q)
//   mode 1: A gathered from g_attn, out row-major [r,e]   (final out)
//   mode 2: A=x, write split-bf16 TRANSPOSED V to g_vt    (V)
// ===========================================================================
#define PITCH 12
#define PLANE (128*PITCH)
#define STG   (4*PLANE)
#define PD    136

__global__ void __launch_bounds__(256)
gemm_mma_kernel(const float* __restrict__ A, const float* __restrict__ W,
                float* __restrict__ out, int mode) {
    __shared__ __align__(16) uint32_t smem[2*STG];   // 49152 B

    int tid  = threadIdx.x;
    int lane = tid & 31;
    int gid  = lane >> 2, tig = lane & 3;
    int warp = tid >> 5;
    int wm = (warp >> 1) * 32, wn = (warp & 1) * 64;
    int r0 = blockIdx.y * 128, n0 = blockIdx.x * 128;

    float4 va[2], vb[2];

    auto ldA = [&](int kb) {
        #pragma unroll
        for (int j = 0; j < 2; j++) {
            int idx = tid + j*256;
            int m = idx >> 2, kq = (idx & 3) * 4;
            if (mode != 1) {
                va[j] = *(const float4*)(A + (size_t)(r0 + m)*Dd + kb + kq);
            } else {
                int r = r0 + m, b = r >> 11, l = r & 2047;
                int c0 = kb + kq;
                va[j] = *(const float4*)(g_attn +
                          (((size_t)(b*Hh + (c0 >> 6)))*Ll + l)*HDh + (c0 & 63));
            }
        }
    };
    auto ldB = [&](int kb) {
        #pragma unroll
        for (int j = 0; j < 2; j++) {
            int idx = tid + j*256;
            int n = idx >> 2, kq = (idx & 3) * 4;
            vb[j] = *(const float4*)(W + (size_t)(n0 + n)*Dd + kb + kq);
        }
    };
    auto splitStore = [&](float4 v, uint32_t* hiP, uint32_t* loP, int m, int kq) {
        float hx = tob(v.x), hy = tob(v.y), hz = tob(v.z), hw = tob(v.w);
        uint2 hiw = { bfpack(hx, hy), bfpack(hz, hw) };
        uint2 low = { bfpack(v.x - hx, v.y - hy), bfpack(v.z - hz, v.w - hw) };
        *(uint2*)&hiP[m*PITCH + (kq >> 1)] = hiw;
        *(uint2*)&loP[m*PITCH + (kq >> 1)] = low;
    };
    auto stAB = [&](int s) {
        uint32_t* base = smem + s*STG;
        #pragma unroll
        for (int j = 0; j < 2; j++) {
            int idx = tid + j*256;
            int m = idx >> 2, kq = (idx & 3) * 4;
            splitStore(va[j], base,           base + PLANE,   m, kq);
            splitStore(vb[j], base + 2*PLANE, base + 3*PLANE, m, kq);
        }
    };

    ldA(0); ldB(0);
    stAB(0);
    __syncthreads();

    float acc[2][8][4] = {};
    const int NIT = Dd / 16;
    for (int it = 0; it < NIT; it++) {
        int s = it & 1;
        if (it + 1 < NIT) { ldA((it+1)*16); ldB((it+1)*16); }
        const uint32_t* Ahi = smem + s*STG;
        const uint32_t* Alo = Ahi + PLANE;
        const uint32_t* Bhi = Ahi + 2*PLANE;
        const uint32_t* Blo = Ahi + 3*PLANE;

        uint32_t af[2][2][4];
        uint32_t bf[8][2][2];
        #pragma unroll
        for (int mt = 0; mt < 2; mt++) {
            int mr = wm + mt*16 + gid;
            af[mt][0][0] = Ahi[ mr     *PITCH + tig    ];
            af[mt][0][1] = Ahi[(mr + 8)*PITCH + tig    ];
            af[mt][0][2] = Ahi[ mr     *PITCH + tig + 4];
            af[mt][0][3] = Ahi[(mr + 8)*PITCH + tig + 4];
            af[mt][1][0] = Alo[ mr     *PITCH + tig    ];
            af[mt][1][1] = Alo[(mr + 8)*PITCH + tig    ];
            af[mt][1][2] = Alo[ mr     *PITCH + tig + 4];
            af[mt][1][3] = Alo[(mr + 8)*PITCH + tig + 4];
        }
        #pragma unroll
        for (int j = 0; j < 8; j++) {
            int nc = wn + j*8 + gid;
            bf[j][0][0] = Bhi[nc*PITCH + tig    ];
            bf[j][0][1] = Bhi[nc*PITCH + tig + 4];
            bf[j][1][0] = Blo[nc*PITCH + tig    ];
            bf[j][1][1] = Blo[nc*PITCH + tig + 4];
        }
        #pragma unroll
        for (int mt = 0; mt < 2; mt++)
            #pragma unroll
            for (int j = 0; j < 8; j++) {
                mma_bf16(acc[mt][j], af[mt][0], bf[j][0]);
                mma_bf16(acc[mt][j], af[mt][0], bf[j][1]);
                mma_bf16(acc[mt][j], af[mt][1], bf[j][0]);
            }

        if (it + 1 < NIT) stAB(s ^ 1);
        __syncthreads();
    }

    float* Ds = (float*)smem;
    #pragma unroll 1
    for (int half = 0; half < 2; half++) {
        __syncthreads();
        if (mode == 2) {
            if ((wm >> 6) == half) {
                int lr0 = wm - half*64;
                #pragma unroll
                for (int mt = 0; mt < 2; mt++)
                    #pragma unroll
                    for (int j = 0; j < 8; j++) {
                        int lr  = lr0 + mt*16 + gid;
                        int col = wn + j*8 + tig*2;
                        Ds[ col   *66 + lr    ] = acc[mt][j][0];
                        Ds[(col+1)*66 + lr    ] = acc[mt][j][1];
                        Ds[ col   *66 + lr + 8] = acc[mt][j][2];
                        Ds[(col+1)*66 + lr + 8] = acc[mt][j][3];
                    }
            }
            __syncthreads();
            int b = r0 >> 11, lb = r0 & 2047;
            int lpbase = (lb + half*64) >> 1;
            #pragma unroll
            for (int i = 0; i < 16; i++) {
                int idx = tid + i*256;
                int lp = idx & 31, c = idx >> 5;
                float2 v = *(const float2*)&Ds[c*66 + 2*lp];
                float hx = tob(v.x), hy = tob(v.y);
                uint2 o = { bfpack(hx, hy), bfpack(v.x - hx, v.y - hy) };
                int bh = b*Hh + (n0 >> 6) + (c >> 6);
                g_vt[((size_t)bh*HDh + (c & 63))*(Ll/2) + lpbase + lp] = o;
            }
            continue;
        }
        if ((wm >> 6) == half) {
            int lr0 = wm - half*64;
            #pragma unroll
            for (int mt = 0; mt < 2; mt++)
                #pragma unroll
                for (int j = 0; j < 8; j++) {
                    int lr  = lr0 + mt*16 + gid;
                    int col = wn + j*8 + tig*2;
                    *(float2*)&Ds[ lr     *PD + col] = make_float2(acc[mt][j][0], acc[mt][j][1]);
                    *(float2*)&Ds[(lr + 8)*PD + col] = make_float2(acc[mt][j][2], acc[mt][j][3]);
                }
        }
        __syncthreads();
        if (mode == 0) {
            int b = r0 >> 11, lb = r0 & 2047;
            #pragma unroll
            for (int i = 0; i < 8; i++) {
                int idx = tid + i*256;
                int lr = idx >> 5, c4 = (idx & 31) * 4;
                int e = n0 + c4, h = e >> 6, hd = e & 63;
                *(float4*)(out + (((size_t)(b*Hh + h))*Ll + lb + half*64 + lr)*HDh + hd)
                    = *(float4*)&Ds[lr*PD + c4];
            }
        } else {
            #pragma unroll
            for (int i = 0; i < 8; i++) {
                int idx = tid + i*256;
                int lr = idx >> 5, c4 = (idx & 31) * 4;
                *(float4*)(out + (size_t)(r0 + half*64 + lr)*Dd + n0 + c4)
                    = *(float4*)&Ds[lr*PD + c4];
            }
        }
    }
}

// ===========================================================================
// fp32 FFMA GEMM — K projection. 128x128 tile, BK=8, 256 threads, 8x8
// micro-tile (4x less LDS per FLOP than the old 64x64/4x4 version).
// k iterates 0..1023 ascending with one sequential FFMA chain per output
// element — BIT-IDENTICAL results to the previous kernel (argmin-safe).
// ===========================================================================
#define FP 132   /* smem pitch */

__global__ void __launch_bounds__(256)
gemm_f32_kernel(const float* __restrict__ A, const float* __restrict__ W,
                float* __restrict__ out) {
    __shared__ float As[2][8][FP];
    __shared__ float Bs[2][8][FP];

    int tid = threadIdx.x;
    int tx  = tid & 15, ty = tid >> 4;
    int r0 = blockIdx.y * 128, n0 = blockIdx.x * 128;

    int lm = tid >> 1;            // 0..127
    int lk = (tid & 1) * 4;       // 0 or 4
    float4 va, vb;

    auto ld = [&](int k0) {
        va = *(const float4*)(A + (size_t)(r0 + lm)*Dd + k0 + lk);
        vb = *(const float4*)(W + (size_t)(n0 + lm)*Dd + k0 + lk);
    };
    auto st = [&](int s) {
        As[s][lk+0][lm]=va.x; As[s][lk+1][lm]=va.y; As[s][lk+2][lm]=va.z; As[s][lk+3][lm]=va.w;
        Bs[s][lk+0][lm]=vb.x; Bs[s][lk+1][lm]=vb.y; Bs[s][lk+2][lm]=vb.z; Bs[s][lk+3][lm]=vb.w;
    };

    ld(0); st(0);
    __syncthreads();

    float acc[8][8] = {};
    const int NIT = Dd / 8;   // 128
    for (int it = 0; it < NIT; it++) {
        int s = it & 1;
        if (it + 1 < NIT) ld((it+1)*8);
        #pragma unroll
        for (int k = 0; k < 8; k++) {
            float4 a0 = *(const float4*)&As[s][k][ty*8];
            float4 a1 = *(const float4*)&As[s][k][ty*8 + 4];
            float4 b0 = *(const float4*)&Bs[s][k][tx*8];
            float4 b1 = *(const float4*)&Bs[s][k][tx*8 + 4];
            float ar[8] = {a0.x,a0.y,a0.z,a0.w,a1.x,a1.y,a1.z,a1.w};
            float br[8] = {b0.x,b0.y,b0.z,b0.w,b1.x,b1.y,b1.z,b1.w};
            #pragma unroll
            for (int i = 0; i < 8; i++)
                #pragma unroll
                for (int j = 0; j < 8; j++)
                    acc[i][j] += ar[i] * br[j];
        }
        if (it + 1 < NIT) st(s ^ 1);
        __syncthreads();
    }

    // scatter to [B,H,L,HD]; j in two float4 groups (same head per group)
    int b = r0 >> 11;
    #pragma unroll
    for (int i = 0; i < 8; i++) {
        int r = r0 + ty*8 + i;
        int l = r & 2047;
        #pragma unroll
        for (int jg = 0; jg < 2; jg++) {
            int e = n0 + tx*8 + jg*4;
            int h = e >> 6, hd = e & 63;
            *(float4*)(out + (((size_t)(b*Hh + h))*Ll + l)*HDh + hd)
                = *(float4*)&acc[i][jg*4];
        }
    }
}

// ===========================================================================
// codebook -> split-bf16 uint2 (one-time prep)
// ===========================================================================
__global__ void __launch_bounds__(256)
cb_split_kernel(const float* __restrict__ codebook) {
    int t = blockIdx.x * 256 + threadIdx.x;
    int row = t >> 5, pr = t & 31;
    float2 v = *(const float2*)(codebook + (size_t)row*HDh + 2*pr);
    float hx = tob(v.x), hy = tob(v.y);
    g_cbs[t] = make_uint2(bfpack(hx, hy), bfpack(v.x - hx, v.y - hy));
}

// ===========================================================================
// VQ (fp32 math UNCHANGED)
// ===========================================================================
__global__ void __launch_bounds__(128)
vq_kernel(const float* __restrict__ codebook, float* __restrict__ dout,
          int out_size) {
    __shared__ float Ks[128][65];
    __shared__ float Cs[64][68];
    __shared__ float c2s[64];
    __shared__ int   bestS[128];
    __shared__ float red[128];

    int tid = threadIdx.x;
    int bh  = blockIdx.y;
    int h   = bh & (Hh - 1);
    int l0  = blockIdx.x * 128;
    size_t kbase = ((size_t)bh * Ll + l0) * HDh;

    for (int idx = tid; idx < 128*64; idx += 128)
        Ks[idx >> 6][idx & 63] = g_k[kbase + idx];
    __syncthreads();

    float kr[64];
    float k0a = 0.f, k1a = 0.f, k2a = 0.f, k3a = 0.f;
    #pragma unroll
    for (int d = 0; d < 64; d += 4) {
        kr[d]   = Ks[tid][d];   k0a += kr[d]  *kr[d];
        kr[d+1] = Ks[tid][d+1]; k1a += kr[d+1]*kr[d+1];
        kr[d+2] = Ks[tid][d+2]; k2a += kr[d+2]*kr[d+2];
        kr[d+3] = Ks[tid][d+3]; k3a += kr[d+3]*kr[d+3];
    }
    float k2 = (k0a + k1a) + (k2a + k3a);

    float best = 3.4e38f;
    int bestc = 0;
    for (int cc = 0; cc < NC; cc += 64) {
        __syncthreads();
        for (int idx = tid; idx < 64*64; idx += 128)
            Cs[idx >> 6][idx & 63] =
                codebook[((size_t)h*NC + cc + (idx >> 6))*HDh + (idx & 63)];
        __syncthreads();
        if (tid < 64) {
            float s0=0,s1=0,s2=0,s3=0;
            #pragma unroll
            for (int d = 0; d < 64; d += 4) {
                float4 cv = *(const float4*)&Cs[tid][d];
                s0 += cv.x*cv.x; s1 += cv.y*cv.y; s2 += cv.z*cv.z; s3 += cv.w*cv.w;
            }
            c2s[tid] = (s0+s1)+(s2+s3);
        }
        __syncthreads();
        #pragma unroll 4
        for (int c = 0; c < 64; c++) {
            float p0=0,p1=0,p2=0,p3=0;
            #pragma unroll
            for (int d = 0; d < 64; d += 4) {
                float4 cv = *(const float4*)&Cs[c][d];
                p0 += kr[d]*cv.x; p1 += kr[d+1]*cv.y;
                p2 += kr[d+2]*cv.z; p3 += kr[d+3]*cv.w;
            }
            float dist = (k2 + c2s[c]) - 2.f*((p0+p1)+(p2+p3));
            if (dist < best) { best = dist; bestc = cc + c; }
        }
    }

    bestS[tid] = bestc;
    red[tid]   = best;
    __syncthreads();
    for (int s = 64; s > 0; s >>= 1) {
        if (tid < s) red[tid] += red[tid + s];
        __syncthreads();
    }
    if (tid == 0)
        g_lred[blockIdx.y * 16 + blockIdx.x] = red[0];
    if (out_size >= BLD + 2 + NTOK)
        dout[BLD + 2 + (size_t)bh*Ll + l0 + tid] = (float)bestc;

    for (int idx = tid; idx < 128*32; idx += 128) {
        int r = idx >> 5, pr = idx & 31;
        g_khat_hl[((size_t)bh*Ll + l0 + r)*32 + pr]
            = g_cbs[((size_t)h*NC + bestS[r])*32 + pr];
    }
}

__global__ void __launch_bounds__(512)
finalize_loss(float* dout, int out_size) {
    __shared__ float red[512];
    int tid = threadIdx.x;
    red[tid] = g_lred[tid];
    __syncthreads();
    for (int s = 256; s > 0; s >>= 1) {
        if (tid < s) red[tid] += red[tid + s];
        __syncthreads();
    }
    if (tid == 0 && out_size >= BLD + 2) {
        float v = red[0] * (1.0f / (float)NTOK);
        dout[BLD]     = v;
        dout[BLD + 1] = v;
    }
}

// ===========================================================================
// bf16x3 mma flash attention (unchanged from round 8)
// ===========================================================================
#define KVP 36   /* uint2 pitch */

__global__ void __launch_bounds__(256)
attn_mma_kernel() {
    __shared__ uint2 Ksm[64*KVP];
    __shared__ uint2 Vsm[64*KVP];

    int tid  = threadIdx.x;
    int lane = tid & 31;
    int gid  = lane >> 2, tig = lane & 3;
    int warp = tid >> 5;
    int bh   = blockIdx.y;
    int i0   = ((int)gridDim.x - 1 - (int)blockIdx.x) * 128;   // heavy first
    int row_start = i0 + warp * 16;
    int r0g  = row_start + gid;
    size_t base = (size_t)bh * Ll * HDh;

    const float scale = 0.125f;
    uint32_t qh[4][4], ql[4][4];
    #pragma unroll
    for (int kb = 0; kb < 4; kb++) {
        #pragma unroll
        for (int cc = 0; cc < 2; cc++)
            #pragma unroll
            for (int rr = 0; rr < 2; rr++) {
                int row = r0g + rr*8;
                int col = kb*16 + tig*2 + cc*8;
                float2 v = *(const float2*)(g_q + base + (size_t)row*HDh + col);
                v.x *= scale; v.y *= scale;
                float hx = tob(v.x), hy = tob(v.y);
                int r = cc*2 + rr;
                qh[kb][r] = bfpack(hx, hy);
                ql[kb][r] = bfpack(v.x - hx, v.y - hy);
            }
    }

    float of[8][4] = {};
    float m0 = -1e30f, m1 = -1e30f, l0 = 0.f, l1 = 0.f;

    const uint2* kh = g_khat_hl + (size_t)bh * Ll * 32;
    const uint2* vt = g_vt     + (size_t)bh * HDh * (Ll/2);

    for (int j0 = 0; j0 < i0 + 128; j0 += 64) {
        #pragma unroll
        for (int p = 0; p < 8; p++) {
            int idx = tid + p*256;
            int key = idx >> 5, pr = idx & 31;
            Ksm[key*KVP + pr] = kh[(size_t)(j0 + key)*32 + pr];
        }
        #pragma unroll
        for (int p = 0; p < 8; p++) {
            int idx = tid + p*256;
            int hd = idx >> 5, kp = idx & 31;
            Vsm[hd*KVP + kp] = vt[(size_t)hd*(Ll/2) + (j0 >> 1) + kp];
        }
        __syncthreads();

        if (j0 <= row_start + 15) {
            float sc[8][4] = {};
            #pragma unroll
            for (int kb = 0; kb < 4; kb++)
                #pragma unroll
                for (int nj = 0; nj < 8; nj++) {
                    uint2 b0 = Ksm[(nj*8+gid)*KVP + kb*8 + tig];
                    uint2 b1 = Ksm[(nj*8+gid)*KVP + kb*8 + tig + 4];
                    uint32_t bhr[2] = {b0.x, b1.x}, blr[2] = {b0.y, b1.y};
                    mma_bf16(sc[nj], qh[kb], bhr);
                    mma_bf16(sc[nj], qh[kb], blr);
                    mma_bf16(sc[nj], ql[kb], bhr);
                }

            if (j0 + 63 > row_start) {
                #pragma unroll
                for (int nj = 0; nj < 8; nj++)
                    #pragma unroll
                    for (int e = 0; e < 2; e++) {
                        int col = j0 + nj*8 + tig*2 + e;
                        if (col > r0g)     sc[nj][e]     = -1e30f;
                        if (col > r0g + 8) sc[nj][2 + e] = -1e30f;
                    }
            }

            float tm0 = -1e30f, tm1 = -1e30f;
            #pragma unroll
            for (int nj = 0; nj < 8; nj++) {
                tm0 = fmaxf(tm0, fmaxf(sc[nj][0], sc[nj][1]));
                tm1 = fmaxf(tm1, fmaxf(sc[nj][2], sc[nj][3]));
            }
            tm0 = fmaxf(tm0, __shfl_xor_sync(0xffffffff, tm0, 1));
            tm0 = fmaxf(tm0, __shfl_xor_sync(0xffffffff, tm0, 2));
            tm1 = fmaxf(tm1, __shfl_xor_sync(0xffffffff, tm1, 1));
            tm1 = fmaxf(tm1, __shfl_xor_sync(0xffffffff, tm1, 2));

            float mn0 = fmaxf(m0, tm0), mn1 = fmaxf(m1, tm1);
            float cr0 = __expf(m0 - mn0), cr1 = __expf(m1 - mn1);
            float rs0 = 0.f, rs1 = 0.f;
            #pragma unroll
            for (int nj = 0; nj < 8; nj++) {
                sc[nj][0] = __expf(sc[nj][0] - mn0);
                sc[nj][1] = __expf(sc[nj][1] - mn0);
                sc[nj][2] = __expf(sc[nj][2] - mn1);
                sc[nj][3] = __expf(sc[nj][3] - mn1);
                rs0 += sc[nj][0] + sc[nj][1];
                rs1 += sc[nj][2] + sc[nj][3];
            }
            rs0 += __shfl_xor_sync(0xffffffff, rs0, 1);
            rs0 += __shfl_xor_sync(0xffffffff, rs0, 2);
            rs1 += __shfl_xor_sync(0xffffffff, rs1, 1);
            rs1 += __shfl_xor_sync(0xffffffff, rs1, 2);
            l0 = l0*cr0 + rs0;
            l1 = l1*cr1 + rs1;
            m0 = mn0; m1 = mn1;
            #pragma unroll
            for (int nj = 0; nj < 8; nj++) {
                of[nj][0] *= cr0; of[nj][1] *= cr0;
                of[nj][2] *= cr1; of[nj][3] *= cr1;
            }

            #pragma unroll
            for (int kb = 0; kb < 4; kb++) {
                float p00 = sc[2*kb][0],   p01 = sc[2*kb][1];
                float p10 = sc[2*kb][2],   p11 = sc[2*kb][3];
                float p20 = sc[2*kb+1][0], p21 = sc[2*kb+1][1];
                float p30 = sc[2*kb+1][2], p31 = sc[2*kb+1][3];
                float h00 = tob(p00), h01 = tob(p01), h10 = tob(p10), h11 = tob(p11);
                float h20 = tob(p20), h21 = tob(p21), h30 = tob(p30), h31 = tob(p31);
                uint32_t ph[4] = { bfpack(h00,h01), bfpack(h10,h11),
                                   bfpack(h20,h21), bfpack(h30,h31) };
                uint32_t pl[4] = { bfpack(p00-h00, p01-h01), bfpack(p10-h10, p11-h11),
                                   bfpack(p20-h20, p21-h21), bfpack(p30-h30, p31-h31) };
                #pragma unroll
                for (int nj = 0; nj < 8; nj++) {
                    uint2 b0 = Vsm[(nj*8+gid)*KVP + kb*8 + tig];
                    uint2 b1 = Vsm[(nj*8+gid)*KVP + kb*8 + tig + 4];
                    uint32_t vh[2] = {b0.x, b1.x}, vl[2] = {b0.y, b1.y};
                    mma_bf16(of[nj], ph, vh);
                    mma_bf16(of[nj], ph, vl);
                    mma_bf16(of[nj], pl, vh);
                }
            }
        }
        __syncthreads();
    }

    float inv0 = 1.0f / l0, inv1 = 1.0f / l1;
    #pragma unroll
    for (int nj = 0; nj < 8; nj++) {
        *(float2*)(g_attn + base + (size_t)r0g*HDh + nj*8 + tig*2)
            = make_float2(of[nj][0]*inv0, of[nj][1]*inv0);
        *(float2*)(g_attn + base + (size_t)(r0g+8)*HDh + nj*8 + tig*2)
            = make_float2(of[nj][2]*inv1, of[nj][3]*inv1);
    }
}

// ===========================================================================
extern "C" void kernel_launch(void* const* d_in, const int* in_sizes, int n_in,
                              void* d_out, int out_size) {
    const float* x  = (const float*)d_in[0];
    const float* Wq = (const float*)d_in[1];
    const float* Wk = (const float*)d_in[2];
    const float* Wv = (const float*)d_in[3];
    const float* Wo = (const float*)d_in[4];
    const float* cb = (const float*)d_in[5];
    float* out = (float*)d_out;

    float *pq, *pk;
    cudaGetSymbolAddress((void**)&pq, g_q);
    cudaGetSymbolAddress((void**)&pk, g_k);

    dim3 ggrid(Dd / 128, (Bb * Ll) / 128);   // (8, 32)

    cb_split_kernel<<<(Hh*NC*32)/256, 256>>>(cb);
    gemm_mma_kernel<<<ggrid, 256>>>(x, Wq, pq, 0);        // Q  (bf16x3)
    gemm_mma_kernel<<<ggrid, 256>>>(x, Wv, nullptr, 2);   // V  (bf16x3 -> g_vt)
    gemm_f32_kernel<<<ggrid, 256>>>(x, Wk, pk);           // K  (fp32 128x128/8x8)

    vq_kernel<<<dim3(Ll/128, Bb*Hh), 128>>>(cb, out, out_size);
    finalize_loss<<<1, 512>>>(out, out_size);
    attn_mma_kernel<<<dim3(Ll/128, Bb*Hh), 256>>>();
    gemm_mma_kernel<<<ggrid, 256>>>(Wo, Wo, out, 1);      // Wo (bf16x3)
}